// round 7
// baseline (speedup 1.0000x reference)
#include <cuda_runtime.h>
#include <cuda_bf16.h>
#include <cstdint>

#define B_   2
#define T_   2048
#define DM_  1024
#define H_   16
#define DH_  64
#define BT_  (B_ * T_)   // 4096

// Scratch (allocation-free rule: device globals)
__device__ __nv_bfloat16 g_ah[BT_ * DM_], g_al[BT_ * DM_];       // x hi/lo
__device__ __nv_bfloat16 g_wth[4 * DM_ * DM_], g_wtl[4 * DM_ * DM_]; // W^T hi/lo (q,k,v,o)
__device__ __nv_bfloat16 g_qh[BT_ * DM_], g_ql[BT_ * DM_];
__device__ __nv_bfloat16 g_kh[BT_ * DM_], g_kl[BT_ * DM_];
__device__ __nv_bfloat16 g_vh[BT_ * DM_], g_vl[BT_ * DM_];
__device__ __nv_bfloat16 g_zh[BT_ * DM_], g_zl[BT_ * DM_];

// ===========================================================================
// Warp-MMA + cp.async helpers (baseline PTX — no tcgen05 on this harness)
// ===========================================================================
__device__ __forceinline__ uint32_t smem_u32(const void* p) {
    uint32_t a;
    asm("{ .reg .u64 t; cvta.to.shared.u64 t, %1; cvt.u32.u64 %0, t; }"
        : "=r"(a) : "l"(p));
    return a;
}

__device__ __forceinline__ void ldsm4(uint32_t* r, uint32_t addr) {
    asm volatile("ldmatrix.sync.aligned.m8n8.x4.shared.b16 {%0,%1,%2,%3}, [%4];"
                 : "=r"(r[0]), "=r"(r[1]), "=r"(r[2]), "=r"(r[3]) : "r"(addr));
}
__device__ __forceinline__ void ldsm4t(uint32_t* r, uint32_t addr) {
    asm volatile("ldmatrix.sync.aligned.m8n8.x4.trans.shared.b16 {%0,%1,%2,%3}, [%4];"
                 : "=r"(r[0]), "=r"(r[1]), "=r"(r[2]), "=r"(r[3]) : "r"(addr));
}

__device__ __forceinline__ void mma16816(float* c, const uint32_t* a,
                                         const uint32_t* b) {
    asm volatile(
        "mma.sync.aligned.m16n8k16.row.col.f32.bf16.bf16.f32 "
        "{%0,%1,%2,%3}, {%4,%5,%6,%7}, {%8,%9}, {%0,%1,%2,%3};"
        : "+f"(c[0]), "+f"(c[1]), "+f"(c[2]), "+f"(c[3])
        : "r"(a[0]), "r"(a[1]), "r"(a[2]), "r"(a[3]), "r"(b[0]), "r"(b[1]));
}

#define CP_ASYNC16(dst, src) \
    asm volatile("cp.async.cg.shared.global [%0], [%1], 16;" :: "r"(dst), "l"(src))
#define CP_COMMIT() asm volatile("cp.async.commit_group;")
#define CP_WAIT1()  asm volatile("cp.async.wait_group 1;")
#define CP_WAIT0()  asm volatile("cp.async.wait_group 0;")

__device__ __forceinline__ float ex2f(float x) {
    float y;
    asm("ex2.approx.f32 %0, %1;" : "=f"(y) : "f"(x));
    return y;
}

// split pair (x,y) into bf16 hi/lo packed regs
__device__ __forceinline__ void split2(float x, float y, uint32_t& hi, uint32_t& lo) {
    __nv_bfloat162 h = __floats2bfloat162_rn(x, y);
    float hx = __bfloat162float(h.x), hy = __bfloat162float(h.y);
    __nv_bfloat162 l = __floats2bfloat162_rn(x - hx, y - hy);
    hi = *(uint32_t*)&h;
    lo = *(uint32_t*)&l;
}

// ===========================================================================
// Conversion kernels
// ===========================================================================
__global__ void conv_split(const float* __restrict__ in,
                           __nv_bfloat16* __restrict__ hi,
                           __nv_bfloat16* __restrict__ lo) {
    int i = (blockIdx.x * 256 + threadIdx.x) * 4;
    float4 v = *(const float4*)(in + i);
    uint32_t h0, l0, h1, l1;
    split2(v.x, v.y, h0, l0);
    split2(v.z, v.w, h1, l1);
    *(uint2*)(hi + i) = make_uint2(h0, h1);
    *(uint2*)(lo + i) = make_uint2(l0, l1);
}

// 4 weight matrices [K,N] row-major -> W^T hi/lo [N,K] into 4 slabs
__global__ void conv_T4(const float* __restrict__ W0, const float* __restrict__ W1,
                        const float* __restrict__ W2, const float* __restrict__ W3,
                        __nv_bfloat16* __restrict__ th, __nv_bfloat16* __restrict__ tl)
{
    __shared__ float t[32][33];
    const float* W = (blockIdx.z == 0) ? W0 : (blockIdx.z == 1) ? W1
                   : (blockIdx.z == 2) ? W2 : W3;
    const size_t slab = (size_t)blockIdx.z * DM_ * DM_;
    const int n0 = blockIdx.x * 32, k0 = blockIdx.y * 32;
    const int tx = threadIdx.x, ty = threadIdx.y;   // (32, 8)
    #pragma unroll
    for (int r = 0; r < 4; r++)
        t[ty * 4 + r][tx] = W[(size_t)(k0 + ty * 4 + r) * DM_ + n0 + tx];
    __syncthreads();
    #pragma unroll
    for (int r = 0; r < 4; r++) {
        float v = t[tx][ty * 4 + r];
        __nv_bfloat16 h = __float2bfloat16(v);
        __nv_bfloat16 l = __float2bfloat16(v - __bfloat162float(h));
        size_t o = slab + (size_t)(n0 + ty * 4 + r) * DM_ + k0 + tx;
        th[o] = h;
        tl[o] = l;
    }
}

// ===========================================================================
// bf16x2-split GEMM, 128x128 tile, BK=32, cp.async 2-stage, 2 CTA/SM.
// MODE 0: QKV — fused RoPE+split epilogue (q additionally scaled by
//         log2(e)/8 so attention can use base-2 exp with a fixed offset).
// MODE 1: out-proj, fp32 epilogue to Cf.
// ===========================================================================
#define GP      80                    // smem row pitch
#define TSZ     (128 * GP)            // 10240 B per operand tile
#define STG     (4 * TSZ)             // 40960 B per stage
#define G_SMEM  (2 * STG)             // 81920 B

#define QSCALE  0.1803368801111204f   // 0.125 * log2(e)

template<int MODE>
__global__ __launch_bounds__(256, 2) void gemm128(
    const __nv_bfloat16* __restrict__ Ah, const __nv_bfloat16* __restrict__ Al,
    const __nv_bfloat16* __restrict__ Bh, const __nv_bfloat16* __restrict__ Bl,
    const float* __restrict__ cs, const float* __restrict__ sn,
    float* __restrict__ Cf,
    __nv_bfloat16* __restrict__ qh, __nv_bfloat16* __restrict__ ql,
    __nv_bfloat16* __restrict__ kh, __nv_bfloat16* __restrict__ kl,
    __nv_bfloat16* __restrict__ vh, __nv_bfloat16* __restrict__ vl)
{
    extern __shared__ __align__(16) char sm[];
    const int tid  = threadIdx.x;
    const int wid  = tid >> 5;
    const int lane = tid & 31;
    const int wm   = wid & 3;
    const int wn   = wid >> 2;
    const int widx = (MODE == 0) ? (blockIdx.x >> 3) : 3;
    const int n0   = (blockIdx.x & 7) * 128;
    const int m0   = blockIdx.y * 128;
    const uint32_t sb = smem_u32(sm);

    const __nv_bfloat16* src[4] = {
        Ah + (size_t)m0 * DM_, Al + (size_t)m0 * DM_,
        Bh + (size_t)widx * DM_ * DM_ + (size_t)n0 * DM_,
        Bl + (size_t)widx * DM_ * DM_ + (size_t)n0 * DM_ };

    const int row = tid >> 2;          // 0..63
    const int cg  = tid & 3;           // 16B chunk in BK row

    #define ISSUE(st_, k0_)                                                    \
        {                                                                      \
            uint32_t d0 = sb + (st_) * STG + row * GP + cg * 16;               \
            _Pragma("unroll")                                                  \
            for (int t = 0; t < 4; t++) {                                      \
                const __nv_bfloat16* g = src[t] + (size_t)row * DM_ + (k0_) + cg * 8; \
                CP_ASYNC16(d0 + t * TSZ,           g);                         \
                CP_ASYNC16(d0 + t * TSZ + 64 * GP, g + (size_t)64 * DM_);      \
            }                                                                  \
            CP_COMMIT();                                                       \
        }

    const uint32_t a_off = (uint32_t)((lane & 15) * GP + (lane >> 4) * 16);
    const uint32_t b_off = (uint32_t)((((lane >> 4) * 8) + (lane & 7)) * GP +
                                      ((lane >> 3) & 1) * 16);

    float acc[2][8][4];
    #pragma unroll
    for (int i = 0; i < 2; i++)
        #pragma unroll
        for (int j = 0; j < 8; j++)
            #pragma unroll
            for (int l = 0; l < 4; l++) acc[i][j][l] = 0.f;

    ISSUE(0, 0);
    ISSUE(1, 32);

    const int NIT = DM_ / 32;   // 32
    for (int c = 0; c < NIT; c++) {
        if (c + 1 < NIT) { CP_WAIT1(); } else { CP_WAIT0(); }
        __syncthreads();

        const uint32_t stb = sb + (c & 1) * STG;
        #pragma unroll
        for (int ks = 0; ks < 2; ks++) {
            uint32_t ahf[2][4], alf[2][4];
            #pragma unroll
            for (int mt = 0; mt < 2; mt++) {
                uint32_t ab = stb + (uint32_t)((wm * 32 + mt * 16) * GP + ks * 32) + a_off;
                ldsm4(ahf[mt], ab);
                ldsm4(alf[mt], ab + TSZ);
            }
            #pragma unroll
            for (int nt = 0; nt < 4; nt++) {
                uint32_t bb = stb + 2 * TSZ +
                              (uint32_t)((wn * 64 + nt * 16) * GP + ks * 32) + b_off;
                uint32_t th[4], tl[4];
                ldsm4(th, bb);
                ldsm4(tl, bb + TSZ);
                #pragma unroll
                for (int mt = 0; mt < 2; mt++) {
                    mma16816(acc[mt][2*nt],   ahf[mt], th);
                    mma16816(acc[mt][2*nt],   ahf[mt], tl);
                    mma16816(acc[mt][2*nt],   alf[mt], th);
                    mma16816(acc[mt][2*nt+1], ahf[mt], th + 2);
                    mma16816(acc[mt][2*nt+1], ahf[mt], tl + 2);
                    mma16816(acc[mt][2*nt+1], alf[mt], th + 2);
                }
            }
        }
        __syncthreads();
        if (c + 2 < NIT) { ISSUE((c & 1), (c + 2) * 32); }
    }

    // ---- epilogue ----
    if (MODE == 1) {
        #pragma unroll
        for (int mt = 0; mt < 2; mt++) {
            int m = m0 + wm * 32 + mt * 16 + (lane >> 2);
            #pragma unroll
            for (int nt = 0; nt < 8; nt++) {
                int n = n0 + wn * 64 + nt * 8 + (lane & 3) * 2;
                *(float2*)(Cf + (size_t)m * DM_ + n) =
                    make_float2(acc[mt][nt][0], acc[mt][nt][1]);
                *(float2*)(Cf + (size_t)(m + 8) * DM_ + n) =
                    make_float2(acc[mt][nt][2], acc[mt][nt][3]);
            }
        }
    } else {
        __nv_bfloat16* dh = (widx == 0) ? qh : (widx == 1) ? kh : vh;
        __nv_bfloat16* dl = (widx == 0) ? ql : (widx == 1) ? kl : vl;
        #pragma unroll
        for (int mt = 0; mt < 2; mt++) {
            int m  = m0 + wm * 32 + mt * 16 + (lane >> 2);
            int t0 = m & (T_ - 1);
            int t1 = (m + 8) & (T_ - 1);
            #pragma unroll
            for (int nt = 0; nt < 8; nt++) {
                int n = n0 + wn * 64 + nt * 8 + (lane & 3) * 2;
                float e0 = acc[mt][nt][0], o0 = acc[mt][nt][1];
                float e1 = acc[mt][nt][2], o1 = acc[mt][nt][3];
                if (widx <= 1) {       // rope on q, k (q also scaled for exp2)
                    int i = (n & 63) >> 1;
                    float c0 = __ldg(cs + t0 * 32 + i), s0 = __ldg(sn + t0 * 32 + i);
                    float c1 = __ldg(cs + t1 * 32 + i), s1 = __ldg(sn + t1 * 32 + i);
                    float sc = (widx == 0) ? QSCALE : 1.f;
                    float a0 = (e0 * c0 - o0 * s0) * sc, b0 = (e0 * s0 + o0 * c0) * sc;
                    float a1 = (e1 * c1 - o1 * s1) * sc, b1 = (e1 * s1 + o1 * c1) * sc;
                    e0 = a0; o0 = b0; e1 = a1; o1 = b1;
                }
                uint32_t h32, l32;
                split2(e0, o0, h32, l32);
                *(uint32_t*)(dh + (size_t)m * DM_ + n) = h32;
                *(uint32_t*)(dl + (size_t)m * DM_ + n) = l32;
                split2(e1, o1, h32, l32);
                *(uint32_t*)(dh + (size_t)(m + 8) * DM_ + n) = h32;
                *(uint32_t*)(dl + (size_t)(m + 8) * DM_ + n) = l32;
            }
        }
    }
    #undef ISSUE
}

// ===========================================================================
// Tensor-core flash attention (bf16 hi/lo split, causal).
// Fixed-base softmax: p = 2^(s' - 26) with s' = s*log2(e) (scale folded into
// q). No running max, no rescaling — l accumulates per-thread; the cross-lane
// reduction happens once in the epilogue. 2 CTAs/SM.
// ===========================================================================
#define PIT   144
#define KL_O  9216
#define VH_O  18432
#define VL_O  27648
#define AST   36864                 // stage size
#define ATT_SMEM (2 * AST)          // 73728
#define SOFF  26.0f                 // fixed exp2 offset

__global__ __launch_bounds__(256, 2) void attn_mma(
    const __nv_bfloat16* __restrict__ qh, const __nv_bfloat16* __restrict__ ql,
    const __nv_bfloat16* __restrict__ kh, const __nv_bfloat16* __restrict__ kl,
    const __nv_bfloat16* __restrict__ vh, const __nv_bfloat16* __restrict__ vl,
    __nv_bfloat16* __restrict__ zh, __nv_bfloat16* __restrict__ zl)
{
    extern __shared__ __align__(16) char sm[];
    const int tid  = threadIdx.x;
    const int lane = tid & 31;
    const int wq   = tid >> 5;
    const int qi   = 15 - blockIdx.x;
    const int bh_  = blockIdx.y;
    const int b    = bh_ >> 4;
    const int h    = bh_ & 15;
    const int q0   = qi * 128;
    const int bT   = b * T_;
    const uint32_t sb = smem_u32(sm);
    const size_t hcol = (size_t)h * DH_;

    // ---- stage Q (hi/lo) through smem, extract A-fragments ----
    {
        int r = tid >> 3, c = tid & 7;
        #pragma unroll
        for (int i = 0; i < 4; i++) {
            int row = r + i * 32;
            size_t g = ((size_t)(bT + q0 + row)) * DM_ + hcol + c * 8;
            *(uint4*)(sm + row * PIT + c * 16)         = *(const uint4*)(qh + g);
            *(uint4*)(sm + 18432 + row * PIT + c * 16) = *(const uint4*)(ql + g);
        }
    }
    __syncthreads();

    uint32_t qfh[4][4], qfl[4][4];
    {
        const uint32_t a_off = (lane & 15) * PIT + (lane >> 4) * 16;
        #pragma unroll
        for (int ks = 0; ks < 4; ks++) {
            ldsm4(qfh[ks], sb + (wq * 16) * PIT + ks * 32 + a_off);
            ldsm4(qfl[ks], sb + 18432 + (wq * 16) * PIT + ks * 32 + a_off);
        }
    }
    __syncthreads();   // Q reads done; smem reusable for K/V stages

    const int nkt = 2 * qi + 2;

    #define AISSUE(st_, k0_)                                                   \
        {                                                                      \
            int r = tid >> 3, cc = tid & 7;                                    \
            uint32_t d = sb + (st_) * AST + r * PIT + cc * 16;                 \
            size_t g = ((size_t)(bT + (k0_) + r)) * DM_ + hcol + cc * 8;       \
            CP_ASYNC16(d,                   kh + g);                           \
            CP_ASYNC16(d + 32 * PIT,        kh + g + 32 * DM_);                \
            CP_ASYNC16(d + KL_O,            kl + g);                           \
            CP_ASYNC16(d + KL_O + 32 * PIT, kl + g + 32 * DM_);                \
            CP_ASYNC16(d + VH_O,            vh + g);                           \
            CP_ASYNC16(d + VH_O + 32 * PIT, vh + g + 32 * DM_);                \
            CP_ASYNC16(d + VL_O,            vl + g);                           \
            CP_ASYNC16(d + VL_O + 32 * PIT, vl + g + 32 * DM_);                \
            CP_COMMIT();                                                       \
        }

    AISSUE(0, 0);
    if (nkt > 1) AISSUE(1, 64);

    float o[8][4];
    #pragma unroll
    for (int i = 0; i < 8; i++)
        #pragma unroll
        for (int j = 0; j < 4; j++) o[i][j] = 0.f;
    float l_lo = 0.f, l_hi = 0.f;

    const uint32_t k_off = ((lane >> 4) * 8 + (lane & 7)) * PIT + ((lane >> 3) & 1) * 16;
    const uint32_t v_off = (lane & 7) * PIT + ((lane >> 3) & 1) * 8 * PIT + (lane >> 4) * 16;
    const int qg_lo = q0 + wq * 16 + (lane >> 2);
    const int qg_hi = qg_lo + 8;

    for (int kt = 0; kt < nkt; kt++) {
        const int k0 = kt * 64;
        if (kt + 1 < nkt) { CP_WAIT1(); } else { CP_WAIT0(); }
        __syncthreads();
        const uint32_t stb = sb + (kt & 1) * AST;

        // ---- S' = Q' K^T (3-pass split) ----
        float sf[8][4];
        #pragma unroll
        for (int i = 0; i < 8; i++)
            #pragma unroll
            for (int j = 0; j < 4; j++) sf[i][j] = 0.f;

        #pragma unroll
        for (int ks = 0; ks < 4; ks++) {
            #pragma unroll
            for (int nt2 = 0; nt2 < 4; nt2++) {
                uint32_t th[4], tl[4];
                ldsm4(th, stb + (nt2 * 16) * PIT + ks * 32 + k_off);
                ldsm4(tl, stb + KL_O + (nt2 * 16) * PIT + ks * 32 + k_off);
                mma16816(sf[2*nt2],   qfh[ks], th);
                mma16816(sf[2*nt2],   qfh[ks], tl);
                mma16816(sf[2*nt2],   qfl[ks], th);
                mma16816(sf[2*nt2+1], qfh[ks], th + 2);
                mma16816(sf[2*nt2+1], qfh[ks], tl + 2);
                mma16816(sf[2*nt2+1], qfl[ks], th + 2);
            }
        }

        if (kt >= nkt - 2) {
            #pragma unroll
            for (int nt = 0; nt < 8; nt++) {
                int kg = k0 + nt * 8 + (lane & 3) * 2;
                if (kg     > qg_lo) sf[nt][0] = -1e30f;
                if (kg + 1 > qg_lo) sf[nt][1] = -1e30f;
                if (kg     > qg_hi) sf[nt][2] = -1e30f;
                if (kg + 1 > qg_hi) sf[nt][3] = -1e30f;
            }
        }

        // ---- p = 2^(s' - 26); accumulate l per-thread ----
        #pragma unroll
        for (int nt = 0; nt < 8; nt++) {
            sf[nt][0] = ex2f(sf[nt][0] - SOFF);
            sf[nt][1] = ex2f(sf[nt][1] - SOFF);
            sf[nt][2] = ex2f(sf[nt][2] - SOFF);
            sf[nt][3] = ex2f(sf[nt][3] - SOFF);
            l_lo += sf[nt][0] + sf[nt][1];
            l_hi += sf[nt][2] + sf[nt][3];
        }

        // ---- O += P V (pack P per-j to keep registers low) ----
        #pragma unroll
        for (int j = 0; j < 4; j++) {
            uint32_t pfh[4], pfl[4];
            split2(sf[2*j][0],   sf[2*j][1],   pfh[0], pfl[0]);
            split2(sf[2*j][2],   sf[2*j][3],   pfh[1], pfl[1]);
            split2(sf[2*j+1][0], sf[2*j+1][1], pfh[2], pfl[2]);
            split2(sf[2*j+1][2], sf[2*j+1][3], pfh[3], pfl[3]);
            #pragma unroll
            for (int d2 = 0; d2 < 4; d2++) {
                uint32_t th[4], tl[4];
                ldsm4t(th, stb + VH_O + (j * 16) * PIT + d2 * 32 + v_off);
                ldsm4t(tl, stb + VL_O + (j * 16) * PIT + d2 * 32 + v_off);
                mma16816(o[2*d2],   pfh, th);
                mma16816(o[2*d2],   pfh, tl);
                mma16816(o[2*d2],   pfl, th);
                mma16816(o[2*d2+1], pfh, th + 2);
                mma16816(o[2*d2+1], pfh, tl + 2);
                mma16816(o[2*d2+1], pfl, th + 2);
            }
        }

        __syncthreads();
        if (kt + 2 < nkt) { AISSUE((kt & 1), (kt + 2) * 64); }
    }
    #undef AISSUE

    // ---- epilogue: reduce l across quad lanes, normalize, split, write ----
    l_lo += __shfl_xor_sync(0xffffffffu, l_lo, 1);
    l_lo += __shfl_xor_sync(0xffffffffu, l_lo, 2);
    l_hi += __shfl_xor_sync(0xffffffffu, l_hi, 1);
    l_hi += __shfl_xor_sync(0xffffffffu, l_hi, 2);
    float il_lo = 1.f / l_lo, il_hi = 1.f / l_hi;
    size_t out_lo = ((size_t)(bT + qg_lo)) * DM_ + hcol + (lane & 3) * 2;
    #pragma unroll
    for (int nt = 0; nt < 8; nt++) {
        uint32_t h32, l32;
        split2(o[nt][0] * il_lo, o[nt][1] * il_lo, h32, l32);
        *(uint32_t*)(zh + out_lo + nt * 8) = h32;
        *(uint32_t*)(zl + out_lo + nt * 8) = l32;
        split2(o[nt][2] * il_hi, o[nt][3] * il_hi, h32, l32);
        *(uint32_t*)(zh + out_lo + 8 * DM_ + nt * 8) = h32;
        *(uint32_t*)(zl + out_lo + 8 * DM_ + nt * 8) = l32;
    }
}

// ---------------------------------------------------------------------------
extern "C" void kernel_launch(void* const* d_in, const int* in_sizes, int n_in,
                              void* d_out, int out_size)
{
    const float* x  = (const float*)d_in[0];
    const float* cs = (const float*)d_in[1];
    const float* sn = (const float*)d_in[2];
    const float* Wq = (const float*)d_in[3];
    const float* Wk = (const float*)d_in[4];
    const float* Wv = (const float*)d_in[5];
    const float* Wo = (const float*)d_in[6];
    float* out = (float*)d_out;

    __nv_bfloat16 *ahp, *alp, *wth, *wtl;
    __nv_bfloat16 *qhp, *qlp, *khp, *klp, *vhp, *vlp, *zhp, *zlp;
    cudaGetSymbolAddress((void**)&ahp, g_ah);
    cudaGetSymbolAddress((void**)&alp, g_al);
    cudaGetSymbolAddress((void**)&wth, g_wth);
    cudaGetSymbolAddress((void**)&wtl, g_wtl);
    cudaGetSymbolAddress((void**)&qhp, g_qh);
    cudaGetSymbolAddress((void**)&qlp, g_ql);
    cudaGetSymbolAddress((void**)&khp, g_kh);
    cudaGetSymbolAddress((void**)&klp, g_kl);
    cudaGetSymbolAddress((void**)&vhp, g_vh);
    cudaGetSymbolAddress((void**)&vlp, g_vl);
    cudaGetSymbolAddress((void**)&zhp, g_zh);
    cudaGetSymbolAddress((void**)&zlp, g_zl);

    cudaFuncSetAttribute(gemm128<0>, cudaFuncAttributeMaxDynamicSharedMemorySize, G_SMEM);
    cudaFuncSetAttribute(gemm128<1>, cudaFuncAttributeMaxDynamicSharedMemorySize, G_SMEM);
    cudaFuncSetAttribute(attn_mma, cudaFuncAttributeMaxDynamicSharedMemorySize, ATT_SMEM);

    // split x; transpose/split all 4 weights in one launch
    conv_split<<<BT_ * DM_ / 1024, 256>>>(x, ahp, alp);
    conv_T4<<<dim3(DM_ / 32, DM_ / 32, 4), dim3(32, 8)>>>(Wq, Wk, Wv, Wo, wth, wtl);

    // fused QKV GEMM + RoPE + split epilogue
    gemm128<0><<<dim3(24, BT_ / 128), 256, G_SMEM>>>(
        ahp, alp, wth, wtl, cs, sn, nullptr,
        qhp, qlp, khp, klp, vhp, vlp);

    attn_mma<<<dim3(16, B_ * H_), 256, ATT_SMEM>>>(qhp, qlp, khp, klp,
                                                   vhp, vlp, zhp, zlp);

    // out = z Wo
    gemm128<1><<<dim3(8, BT_ / 128), 256, G_SMEM>>>(
        zhp, zlp, wth, wtl, cs, sn, out,
        nullptr, nullptr, nullptr, nullptr, nullptr, nullptr);
}

// round 8
// speedup vs baseline: 1.1348x; 1.1348x over previous
#include <cuda_runtime.h>
#include <cuda_bf16.h>
#include <cstdint>

#define B_   2
#define T_   2048
#define DM_  1024
#define H_   16
#define DH_  64
#define BT_  (B_ * T_)   // 4096

// Scratch (allocation-free rule: device globals)
__device__ __nv_bfloat16 g_ah[BT_ * DM_], g_al[BT_ * DM_];           // x hi/lo
__device__ __nv_bfloat16 g_wh[4 * DM_ * DM_], g_wl[4 * DM_ * DM_];   // W hi/lo, [K,N] layout
__device__ __nv_bfloat16 g_qh[BT_ * DM_], g_ql[BT_ * DM_];
__device__ __nv_bfloat16 g_kh[BT_ * DM_], g_kl[BT_ * DM_];
__device__ __nv_bfloat16 g_vh[BT_ * DM_], g_vl[BT_ * DM_];
__device__ __nv_bfloat16 g_zh[BT_ * DM_], g_zl[BT_ * DM_];

// ===========================================================================
// Warp-MMA + cp.async helpers (baseline PTX — no tcgen05 on this harness)
// ===========================================================================
__device__ __forceinline__ uint32_t smem_u32(const void* p) {
    uint32_t a;
    asm("{ .reg .u64 t; cvta.to.shared.u64 t, %1; cvt.u32.u64 %0, t; }"
        : "=r"(a) : "l"(p));
    return a;
}

__device__ __forceinline__ void ldsm4(uint32_t* r, uint32_t addr) {
    asm volatile("ldmatrix.sync.aligned.m8n8.x4.shared.b16 {%0,%1,%2,%3}, [%4];"
                 : "=r"(r[0]), "=r"(r[1]), "=r"(r[2]), "=r"(r[3]) : "r"(addr));
}
__device__ __forceinline__ void ldsm4t(uint32_t* r, uint32_t addr) {
    asm volatile("ldmatrix.sync.aligned.m8n8.x4.trans.shared.b16 {%0,%1,%2,%3}, [%4];"
                 : "=r"(r[0]), "=r"(r[1]), "=r"(r[2]), "=r"(r[3]) : "r"(addr));
}

__device__ __forceinline__ void mma16816(float* c, const uint32_t* a,
                                         const uint32_t* b) {
    asm volatile(
        "mma.sync.aligned.m16n8k16.row.col.f32.bf16.bf16.f32 "
        "{%0,%1,%2,%3}, {%4,%5,%6,%7}, {%8,%9}, {%0,%1,%2,%3};"
        : "+f"(c[0]), "+f"(c[1]), "+f"(c[2]), "+f"(c[3])
        : "r"(a[0]), "r"(a[1]), "r"(a[2]), "r"(a[3]), "r"(b[0]), "r"(b[1]));
}

#define CP_ASYNC16(dst, src) \
    asm volatile("cp.async.cg.shared.global [%0], [%1], 16;" :: "r"(dst), "l"(src))
#define CP_COMMIT() asm volatile("cp.async.commit_group;")
#define CP_WAIT1()  asm volatile("cp.async.wait_group 1;")
#define CP_WAIT0()  asm volatile("cp.async.wait_group 0;")

__device__ __forceinline__ float ex2f(float x) {
    float y;
    asm("ex2.approx.f32 %0, %1;" : "=f"(y) : "f"(x));
    return y;
}

// split pair (x,y) into bf16 hi/lo packed regs
__device__ __forceinline__ void split2(float x, float y, uint32_t& hi, uint32_t& lo) {
    __nv_bfloat162 h = __floats2bfloat162_rn(x, y);
    float hx = __bfloat162float(h.x), hy = __bfloat162float(h.y);
    __nv_bfloat162 l = __floats2bfloat162_rn(x - hx, y - hy);
    hi = *(uint32_t*)&h;
    lo = *(uint32_t*)&l;
}

// ===========================================================================
// Conversion kernels (pure elementwise — no transpose needed any more)
// ===========================================================================
__global__ void conv_split(const float* __restrict__ in,
                           __nv_bfloat16* __restrict__ hi,
                           __nv_bfloat16* __restrict__ lo) {
    int i = (blockIdx.x * 256 + threadIdx.x) * 4;
    float4 v = *(const float4*)(in + i);
    uint32_t h0, l0, h1, l1;
    split2(v.x, v.y, h0, l0);
    split2(v.z, v.w, h1, l1);
    *(uint2*)(hi + i) = make_uint2(h0, h1);
    *(uint2*)(lo + i) = make_uint2(l0, l1);
}

// 4 weight matrices [K,N] fp32 -> hi/lo bf16, same layout, 4 slabs
__global__ void conv_splitW(const float* __restrict__ W0, const float* __restrict__ W1,
                            const float* __restrict__ W2, const float* __restrict__ W3,
                            __nv_bfloat16* __restrict__ th, __nv_bfloat16* __restrict__ tl)
{
    const float* W = (blockIdx.y == 0) ? W0 : (blockIdx.y == 1) ? W1
                   : (blockIdx.y == 2) ? W2 : W3;
    size_t base = (size_t)blockIdx.y * DM_ * DM_;
    int i = (blockIdx.x * 256 + threadIdx.x) * 4;
    float4 v = *(const float4*)(W + i);
    uint32_t h0, l0, h1, l1;
    split2(v.x, v.y, h0, l0);
    split2(v.z, v.w, h1, l1);
    *(uint2*)(th + base + i) = make_uint2(h0, h1);
    *(uint2*)(tl + base + i) = make_uint2(l0, l1);
}

// ===========================================================================
// bf16x2-split GEMM, 128x128 tile, BK=32, cp.async 2-stage, 2 CTA/SM.
// B operand now loaded directly from W [K,N] row-major; fragments via
// ldmatrix.trans (same pattern as the validated V path in attention).
// MODE 0: QKV — fused RoPE+split epilogue. MODE 1: out-proj, fp32 epilogue.
// ===========================================================================
#define GP      80                    // A smem row pitch
#define TSZA    (128 * GP)            // A tile: 10240 B
#define PITB    272                   // B smem row pitch (128 bf16 + 16B pad)
#define TSZB    (32 * PITB)           // B tile: 8704 B
#define BH_O    (2 * TSZA)            // 20480
#define BL_O    (BH_O + TSZB)         // 29184
#define STG     (BL_O + TSZB)         // 37888 per stage
#define G_SMEM  (2 * STG)             // 75776

#define QSCALE  0.1803368801111204f   // 0.125 * log2(e)

template<int MODE>
__global__ __launch_bounds__(256, 2) void gemm128(
    const __nv_bfloat16* __restrict__ Ah, const __nv_bfloat16* __restrict__ Al,
    const __nv_bfloat16* __restrict__ Wh, const __nv_bfloat16* __restrict__ Wl,
    const float* __restrict__ cs, const float* __restrict__ sn,
    float* __restrict__ Cf,
    __nv_bfloat16* __restrict__ qh, __nv_bfloat16* __restrict__ ql,
    __nv_bfloat16* __restrict__ kh, __nv_bfloat16* __restrict__ kl,
    __nv_bfloat16* __restrict__ vh, __nv_bfloat16* __restrict__ vl)
{
    extern __shared__ __align__(16) char sm[];
    const int tid  = threadIdx.x;
    const int wid  = tid >> 5;
    const int lane = tid & 31;
    const int wm   = wid & 3;
    const int wn   = wid >> 2;
    const int widx = (MODE == 0) ? (blockIdx.x >> 3) : 3;
    const int n0   = (blockIdx.x & 7) * 128;
    const int m0   = blockIdx.y * 128;
    const uint32_t sb = smem_u32(sm);

    const __nv_bfloat16* gAh = Ah + (size_t)m0 * DM_;
    const __nv_bfloat16* gAl = Al + (size_t)m0 * DM_;
    const __nv_bfloat16* gWh = Wh + (size_t)widx * DM_ * DM_ + n0;
    const __nv_bfloat16* gWl = Wl + (size_t)widx * DM_ * DM_ + n0;

    const int arow = tid >> 2;         // 0..63
    const int acg  = tid & 3;
    const int brow = tid >> 4;         // 0..15
    const int bcg  = tid & 15;

    #define ISSUE(st_, k0_)                                                    \
        {                                                                      \
            uint32_t dA = sb + (st_) * STG + arow * GP + acg * 16;             \
            const __nv_bfloat16* ga = gAh + (size_t)arow * DM_ + (k0_) + acg * 8; \
            const __nv_bfloat16* gl = gAl + (size_t)arow * DM_ + (k0_) + acg * 8; \
            CP_ASYNC16(dA,                  ga);                               \
            CP_ASYNC16(dA + 64 * GP,        ga + (size_t)64 * DM_);            \
            CP_ASYNC16(dA + TSZA,           gl);                               \
            CP_ASYNC16(dA + TSZA + 64 * GP, gl + (size_t)64 * DM_);            \
            uint32_t dB = sb + (st_) * STG + BH_O + brow * PITB + bcg * 16;    \
            const __nv_bfloat16* gh = gWh + (size_t)((k0_) + brow) * DM_ + bcg * 8; \
            const __nv_bfloat16* gw = gWl + (size_t)((k0_) + brow) * DM_ + bcg * 8; \
            CP_ASYNC16(dB,                    gh);                             \
            CP_ASYNC16(dB + 16 * PITB,        gh + (size_t)16 * DM_);          \
            CP_ASYNC16(dB + TSZB,             gw);                             \
            CP_ASYNC16(dB + TSZB + 16 * PITB, gw + (size_t)16 * DM_);          \
            CP_COMMIT();                                                       \
        }

    const uint32_t a_off = (uint32_t)((lane & 15) * GP + (lane >> 4) * 16);
    const uint32_t b_off = (uint32_t)((lane & 7) * PITB +
                                      ((lane >> 3) & 1) * 8 * PITB + (lane >> 4) * 16);

    float acc[2][8][4];
    #pragma unroll
    for (int i = 0; i < 2; i++)
        #pragma unroll
        for (int j = 0; j < 8; j++)
            #pragma unroll
            for (int l = 0; l < 4; l++) acc[i][j][l] = 0.f;

    ISSUE(0, 0);
    ISSUE(1, 32);

    const int NIT = DM_ / 32;   // 32
    for (int c = 0; c < NIT; c++) {
        if (c + 1 < NIT) { CP_WAIT1(); } else { CP_WAIT0(); }
        __syncthreads();

        const uint32_t stb = sb + (c & 1) * STG;
        #pragma unroll
        for (int ks = 0; ks < 2; ks++) {
            uint32_t ahf[2][4], alf[2][4];
            #pragma unroll
            for (int mt = 0; mt < 2; mt++) {
                uint32_t ab = stb + (uint32_t)((wm * 32 + mt * 16) * GP + ks * 32) + a_off;
                ldsm4(ahf[mt], ab);
                ldsm4(alf[mt], ab + TSZA);
            }
            #pragma unroll
            for (int nt = 0; nt < 4; nt++) {
                uint32_t bb = stb + BH_O + (uint32_t)(ks * 16 * PITB +
                              wn * 128 + nt * 32) + b_off;
                uint32_t th[4], tl[4];
                ldsm4t(th, bb);
                ldsm4t(tl, bb + TSZB);
                #pragma unroll
                for (int mt = 0; mt < 2; mt++) {
                    mma16816(acc[mt][2*nt],   ahf[mt], th);
                    mma16816(acc[mt][2*nt],   ahf[mt], tl);
                    mma16816(acc[mt][2*nt],   alf[mt], th);
                    mma16816(acc[mt][2*nt+1], ahf[mt], th + 2);
                    mma16816(acc[mt][2*nt+1], ahf[mt], tl + 2);
                    mma16816(acc[mt][2*nt+1], alf[mt], th + 2);
                }
            }
        }
        __syncthreads();
        if (c + 2 < NIT) { ISSUE((c & 1), (c + 2) * 32); }
    }

    // ---- epilogue ----
    if (MODE == 1) {
        #pragma unroll
        for (int mt = 0; mt < 2; mt++) {
            int m = m0 + wm * 32 + mt * 16 + (lane >> 2);
            #pragma unroll
            for (int nt = 0; nt < 8; nt++) {
                int n = n0 + wn * 64 + nt * 8 + (lane & 3) * 2;
                *(float2*)(Cf + (size_t)m * DM_ + n) =
                    make_float2(acc[mt][nt][0], acc[mt][nt][1]);
                *(float2*)(Cf + (size_t)(m + 8) * DM_ + n) =
                    make_float2(acc[mt][nt][2], acc[mt][nt][3]);
            }
        }
    } else {
        __nv_bfloat16* dh = (widx == 0) ? qh : (widx == 1) ? kh : vh;
        __nv_bfloat16* dl = (widx == 0) ? ql : (widx == 1) ? kl : vl;
        #pragma unroll
        for (int mt = 0; mt < 2; mt++) {
            int m  = m0 + wm * 32 + mt * 16 + (lane >> 2);
            int t0 = m & (T_ - 1);
            int t1 = (m + 8) & (T_ - 1);
            #pragma unroll
            for (int nt = 0; nt < 8; nt++) {
                int n = n0 + wn * 64 + nt * 8 + (lane & 3) * 2;
                float e0 = acc[mt][nt][0], o0 = acc[mt][nt][1];
                float e1 = acc[mt][nt][2], o1 = acc[mt][nt][3];
                if (widx <= 1) {       // rope on q, k (q also scaled for exp2)
                    int i = (n & 63) >> 1;
                    float c0 = __ldg(cs + t0 * 32 + i), s0 = __ldg(sn + t0 * 32 + i);
                    float c1 = __ldg(cs + t1 * 32 + i), s1 = __ldg(sn + t1 * 32 + i);
                    float sc = (widx == 0) ? QSCALE : 1.f;
                    float a0 = (e0 * c0 - o0 * s0) * sc, b0 = (e0 * s0 + o0 * c0) * sc;
                    float a1 = (e1 * c1 - o1 * s1) * sc, b1 = (e1 * s1 + o1 * c1) * sc;
                    e0 = a0; o0 = b0; e1 = a1; o1 = b1;
                }
                uint32_t h32, l32;
                split2(e0, o0, h32, l32);
                *(uint32_t*)(dh + (size_t)m * DM_ + n) = h32;
                *(uint32_t*)(dl + (size_t)m * DM_ + n) = l32;
                split2(e1, o1, h32, l32);
                *(uint32_t*)(dh + (size_t)(m + 8) * DM_ + n) = h32;
                *(uint32_t*)(dl + (size_t)(m + 8) * DM_ + n) = l32;
            }
        }
    }
    #undef ISSUE
}

// ===========================================================================
// Tensor-core flash attention (bf16 hi/lo split, causal, fixed-base exp2).
// BALANCED: each CTA handles q-tile pair (15-bx, bx) => exactly 34 k-tiles
// per CTA; 256 uniform CTAs, single wave at 2 CTA/SM.
// ===========================================================================
#define PIT   144
#define KL_O  9216
#define VH_O  18432
#define VL_O  27648
#define AST   36864                 // stage size
#define ATT_SMEM (2 * AST)          // 73728
#define SOFF  26.0f                 // fixed exp2 offset

__global__ __launch_bounds__(256, 2) void attn_mma(
    const __nv_bfloat16* __restrict__ qh, const __nv_bfloat16* __restrict__ ql,
    const __nv_bfloat16* __restrict__ kh, const __nv_bfloat16* __restrict__ kl,
    const __nv_bfloat16* __restrict__ vh, const __nv_bfloat16* __restrict__ vl,
    __nv_bfloat16* __restrict__ zh, __nv_bfloat16* __restrict__ zl)
{
    extern __shared__ __align__(16) char sm[];
    const int tid  = threadIdx.x;
    const int lane = tid & 31;
    const int wq   = tid >> 5;
    const int bx   = blockIdx.x;          // 0..7
    const int bh_  = blockIdx.y;
    const int b    = bh_ >> 4;
    const int h    = bh_ & 15;
    const int bT   = b * T_;
    const uint32_t sb = smem_u32(sm);
    const size_t hcol = (size_t)h * DH_;

    const uint32_t k_off = ((lane >> 4) * 8 + (lane & 7)) * PIT + ((lane >> 3) & 1) * 16;
    const uint32_t v_off = (lane & 7) * PIT + ((lane >> 3) & 1) * 8 * PIT + (lane >> 4) * 16;

    #define AISSUE(st_, k0_)                                                   \
        {                                                                      \
            int r = tid >> 3, cc = tid & 7;                                    \
            uint32_t d = sb + (st_) * AST + r * PIT + cc * 16;                 \
            size_t g = ((size_t)(bT + (k0_) + r)) * DM_ + hcol + cc * 8;       \
            CP_ASYNC16(d,                   kh + g);                           \
            CP_ASYNC16(d + 32 * PIT,        kh + g + 32 * DM_);                \
            CP_ASYNC16(d + KL_O,            kl + g);                           \
            CP_ASYNC16(d + KL_O + 32 * PIT, kl + g + 32 * DM_);                \
            CP_ASYNC16(d + VH_O,            vh + g);                           \
            CP_ASYNC16(d + VH_O + 32 * PIT, vh + g + 32 * DM_);                \
            CP_ASYNC16(d + VL_O,            vl + g);                           \
            CP_ASYNC16(d + VL_O + 32 * PIT, vl + g + 32 * DM_);                \
            CP_COMMIT();                                                       \
        }

    #pragma unroll 1
    for (int ph = 0; ph < 2; ph++) {
        const int qi = ph ? bx : 15 - bx;     // heavy tile first
        const int q0 = qi * 128;
        const int nkt = 2 * qi + 2;
        const int qg_lo = q0 + wq * 16 + (lane >> 2);
        const int qg_hi = qg_lo + 8;

        // ---- stage Q (hi/lo) through smem, extract A-fragments ----
        {
            int r = tid >> 3, c = tid & 7;
            #pragma unroll
            for (int i = 0; i < 4; i++) {
                int row = r + i * 32;
                size_t g = ((size_t)(bT + q0 + row)) * DM_ + hcol + c * 8;
                *(uint4*)(sm + row * PIT + c * 16)         = *(const uint4*)(qh + g);
                *(uint4*)(sm + 18432 + row * PIT + c * 16) = *(const uint4*)(ql + g);
            }
        }
        __syncthreads();

        uint32_t qfh[4][4], qfl[4][4];
        {
            const uint32_t a_off = (lane & 15) * PIT + (lane >> 4) * 16;
            #pragma unroll
            for (int ks = 0; ks < 4; ks++) {
                ldsm4(qfh[ks], sb + (wq * 16) * PIT + ks * 32 + a_off);
                ldsm4(qfl[ks], sb + 18432 + (wq * 16) * PIT + ks * 32 + a_off);
            }
        }
        __syncthreads();   // Q reads done; smem reusable for K/V stages

        AISSUE(0, 0);
        if (nkt > 1) AISSUE(1, 64);

        float o[8][4];
        #pragma unroll
        for (int i = 0; i < 8; i++)
            #pragma unroll
            for (int j = 0; j < 4; j++) o[i][j] = 0.f;
        float l_lo = 0.f, l_hi = 0.f;

        for (int kt = 0; kt < nkt; kt++) {
            const int k0 = kt * 64;
            if (kt + 1 < nkt) { CP_WAIT1(); } else { CP_WAIT0(); }
            __syncthreads();
            const uint32_t stb = sb + (kt & 1) * AST;

            // ---- S' = Q' K^T (3-pass split) ----
            float sf[8][4];
            #pragma unroll
            for (int i = 0; i < 8; i++)
                #pragma unroll
                for (int j = 0; j < 4; j++) sf[i][j] = 0.f;

            #pragma unroll
            for (int ks = 0; ks < 4; ks++) {
                #pragma unroll
                for (int nt2 = 0; nt2 < 4; nt2++) {
                    uint32_t th[4], tl[4];
                    ldsm4(th, stb + (nt2 * 16) * PIT + ks * 32 + k_off);
                    ldsm4(tl, stb + KL_O + (nt2 * 16) * PIT + ks * 32 + k_off);
                    mma16816(sf[2*nt2],   qfh[ks], th);
                    mma16816(sf[2*nt2],   qfh[ks], tl);
                    mma16816(sf[2*nt2],   qfl[ks], th);
                    mma16816(sf[2*nt2+1], qfh[ks], th + 2);
                    mma16816(sf[2*nt2+1], qfh[ks], tl + 2);
                    mma16816(sf[2*nt2+1], qfl[ks], th + 2);
                }
            }

            if (kt >= nkt - 2) {
                #pragma unroll
                for (int nt = 0; nt < 8; nt++) {
                    int kg = k0 + nt * 8 + (lane & 3) * 2;
                    if (kg     > qg_lo) sf[nt][0] = -1e30f;
                    if (kg + 1 > qg_lo) sf[nt][1] = -1e30f;
                    if (kg     > qg_hi) sf[nt][2] = -1e30f;
                    if (kg + 1 > qg_hi) sf[nt][3] = -1e30f;
                }
            }

            // ---- p = 2^(s' - 26); accumulate l per-thread ----
            #pragma unroll
            for (int nt = 0; nt < 8; nt++) {
                sf[nt][0] = ex2f(sf[nt][0] - SOFF);
                sf[nt][1] = ex2f(sf[nt][1] - SOFF);
                sf[nt][2] = ex2f(sf[nt][2] - SOFF);
                sf[nt][3] = ex2f(sf[nt][3] - SOFF);
                l_lo += sf[nt][0] + sf[nt][1];
                l_hi += sf[nt][2] + sf[nt][3];
            }

            // ---- O += P V (pack P per-j to keep registers low) ----
            #pragma unroll
            for (int j = 0; j < 4; j++) {
                uint32_t pfh[4], pfl[4];
                split2(sf[2*j][0],   sf[2*j][1],   pfh[0], pfl[0]);
                split2(sf[2*j][2],   sf[2*j][3],   pfh[1], pfl[1]);
                split2(sf[2*j+1][0], sf[2*j+1][1], pfh[2], pfl[2]);
                split2(sf[2*j+1][2], sf[2*j+1][3], pfh[3], pfl[3]);
                #pragma unroll
                for (int d2 = 0; d2 < 4; d2++) {
                    uint32_t th[4], tl[4];
                    ldsm4t(th, stb + VH_O + (j * 16) * PIT + d2 * 32 + v_off);
                    ldsm4t(tl, stb + VL_O + (j * 16) * PIT + d2 * 32 + v_off);
                    mma16816(o[2*d2],   pfh, th);
                    mma16816(o[2*d2],   pfh, tl);
                    mma16816(o[2*d2],   pfl, th);
                    mma16816(o[2*d2+1], pfh, th + 2);
                    mma16816(o[2*d2+1], pfh, tl + 2);
                    mma16816(o[2*d2+1], pfl, th + 2);
                }
            }

            __syncthreads();
            if (kt + 2 < nkt) { AISSUE((kt & 1), (kt + 2) * 64); }
        }

        // ---- epilogue: reduce l across quad lanes, normalize, split, write ----
        l_lo += __shfl_xor_sync(0xffffffffu, l_lo, 1);
        l_lo += __shfl_xor_sync(0xffffffffu, l_lo, 2);
        l_hi += __shfl_xor_sync(0xffffffffu, l_hi, 1);
        l_hi += __shfl_xor_sync(0xffffffffu, l_hi, 2);
        float il_lo = 1.f / l_lo, il_hi = 1.f / l_hi;
        size_t out_lo = ((size_t)(bT + qg_lo)) * DM_ + hcol + (lane & 3) * 2;
        #pragma unroll
        for (int nt = 0; nt < 8; nt++) {
            uint32_t h32, l32;
            split2(o[nt][0] * il_lo, o[nt][1] * il_lo, h32, l32);
            *(uint32_t*)(zh + out_lo + nt * 8) = h32;
            *(uint32_t*)(zl + out_lo + nt * 8) = l32;
            split2(o[nt][2] * il_hi, o[nt][3] * il_hi, h32, l32);
            *(uint32_t*)(zh + out_lo + 8 * DM_ + nt * 8) = h32;
            *(uint32_t*)(zl + out_lo + 8 * DM_ + nt * 8) = l32;
        }
    }
    #undef AISSUE
}

// ---------------------------------------------------------------------------
extern "C" void kernel_launch(void* const* d_in, const int* in_sizes, int n_in,
                              void* d_out, int out_size)
{
    const float* x  = (const float*)d_in[0];
    const float* cs = (const float*)d_in[1];
    const float* sn = (const float*)d_in[2];
    const float* Wq = (const float*)d_in[3];
    const float* Wk = (const float*)d_in[4];
    const float* Wv = (const float*)d_in[5];
    const float* Wo = (const float*)d_in[6];
    float* out = (float*)d_out;

    __nv_bfloat16 *ahp, *alp, *whp, *wlp;
    __nv_bfloat16 *qhp, *qlp, *khp, *klp, *vhp, *vlp, *zhp, *zlp;
    cudaGetSymbolAddress((void**)&ahp, g_ah);
    cudaGetSymbolAddress((void**)&alp, g_al);
    cudaGetSymbolAddress((void**)&whp, g_wh);
    cudaGetSymbolAddress((void**)&wlp, g_wl);
    cudaGetSymbolAddress((void**)&qhp, g_qh);
    cudaGetSymbolAddress((void**)&qlp, g_ql);
    cudaGetSymbolAddress((void**)&khp, g_kh);
    cudaGetSymbolAddress((void**)&klp, g_kl);
    cudaGetSymbolAddress((void**)&vhp, g_vh);
    cudaGetSymbolAddress((void**)&vlp, g_vl);
    cudaGetSymbolAddress((void**)&zhp, g_zh);
    cudaGetSymbolAddress((void**)&zlp, g_zl);

    cudaFuncSetAttribute(gemm128<0>, cudaFuncAttributeMaxDynamicSharedMemorySize, G_SMEM);
    cudaFuncSetAttribute(gemm128<1>, cudaFuncAttributeMaxDynamicSharedMemorySize, G_SMEM);
    cudaFuncSetAttribute(attn_mma, cudaFuncAttributeMaxDynamicSharedMemorySize, ATT_SMEM);

    // elementwise hi/lo splits (no transpose — GEMM consumes W [K,N] directly)
    conv_split<<<BT_ * DM_ / 1024, 256>>>(x, ahp, alp);
    conv_splitW<<<dim3(DM_ * DM_ / 1024, 4), 256>>>(Wq, Wk, Wv, Wo, whp, wlp);

    // fused QKV GEMM + RoPE + split epilogue
    gemm128<0><<<dim3(24, BT_ / 128), 256, G_SMEM>>>(
        ahp, alp, whp, wlp, cs, sn, nullptr,
        qhp, qlp, khp, klp, vhp, vlp);

    attn_mma<<<dim3(8, B_ * H_), 256, ATT_SMEM>>>(qhp, qlp, khp, klp,
                                                  vhp, vlp, zhp, zlp);

    // out = z Wo
    gemm128<1><<<dim3(8, BT_ / 128), 256, G_SMEM>>>(
        zhp, zlp, whp, wlp, cs, sn, out,
        nullptr, nullptr, nullptr, nullptr, nullptr, nullptr);
}

// round 9
// speedup vs baseline: 1.4124x; 1.2446x over previous
#include <cuda_runtime.h>
#include <cuda_bf16.h>
#include <cuda_fp16.h>
#include <cstdint>

#define B_   2
#define T_   2048
#define DM_  1024
#define H_   16
#define DH_  64
#define BT_  (B_ * T_)   // 4096

// Scratch (allocation-free rule: device globals)
__device__ __half g_ah[BT_ * DM_], g_al[BT_ * DM_];            // x hi/lo (fp16)
__device__ __half g_w[4 * DM_ * DM_];                          // W single fp16, [K,N], 4 slabs
__device__ __nv_bfloat16 g_qh[BT_ * DM_], g_ql[BT_ * DM_];     // attention operands: bf16 hi/lo
__device__ __nv_bfloat16 g_kh[BT_ * DM_], g_kl[BT_ * DM_];
__device__ __nv_bfloat16 g_vh[BT_ * DM_], g_vl[BT_ * DM_];
__device__ __half g_zh[BT_ * DM_], g_zl[BT_ * DM_];            // z hi/lo (fp16)

// ===========================================================================
// Warp-MMA + cp.async helpers (baseline PTX — no tcgen05 on this harness)
// ===========================================================================
__device__ __forceinline__ uint32_t smem_u32(const void* p) {
    uint32_t a;
    asm("{ .reg .u64 t; cvta.to.shared.u64 t, %1; cvt.u32.u64 %0, t; }"
        : "=r"(a) : "l"(p));
    return a;
}

__device__ __forceinline__ void ldsm4(uint32_t* r, uint32_t addr) {
    asm volatile("ldmatrix.sync.aligned.m8n8.x4.shared.b16 {%0,%1,%2,%3}, [%4];"
                 : "=r"(r[0]), "=r"(r[1]), "=r"(r[2]), "=r"(r[3]) : "r"(addr));
}
__device__ __forceinline__ void ldsm4t(uint32_t* r, uint32_t addr) {
    asm volatile("ldmatrix.sync.aligned.m8n8.x4.trans.shared.b16 {%0,%1,%2,%3}, [%4];"
                 : "=r"(r[0]), "=r"(r[1]), "=r"(r[2]), "=r"(r[3]) : "r"(addr));
}

// bf16 MMA (attention)
__device__ __forceinline__ void mma16816(float* c, const uint32_t* a,
                                         const uint32_t* b) {
    asm volatile(
        "mma.sync.aligned.m16n8k16.row.col.f32.bf16.bf16.f32 "
        "{%0,%1,%2,%3}, {%4,%5,%6,%7}, {%8,%9}, {%0,%1,%2,%3};"
        : "+f"(c[0]), "+f"(c[1]), "+f"(c[2]), "+f"(c[3])
        : "r"(a[0]), "r"(a[1]), "r"(a[2]), "r"(a[3]), "r"(b[0]), "r"(b[1]));
}

// fp16 MMA (GEMMs)
__device__ __forceinline__ void mma16816h(float* c, const uint32_t* a,
                                          const uint32_t* b) {
    asm volatile(
        "mma.sync.aligned.m16n8k16.row.col.f32.f16.f16.f32 "
        "{%0,%1,%2,%3}, {%4,%5,%6,%7}, {%8,%9}, {%0,%1,%2,%3};"
        : "+f"(c[0]), "+f"(c[1]), "+f"(c[2]), "+f"(c[3])
        : "r"(a[0]), "r"(a[1]), "r"(a[2]), "r"(a[3]), "r"(b[0]), "r"(b[1]));
}

#define CP_ASYNC16(dst, src) \
    asm volatile("cp.async.cg.shared.global [%0], [%1], 16;" :: "r"(dst), "l"(src))
#define CP_COMMIT() asm volatile("cp.async.commit_group;")
#define CP_WAIT1()  asm volatile("cp.async.wait_group 1;")
#define CP_WAIT0()  asm volatile("cp.async.wait_group 0;")

__device__ __forceinline__ float ex2f(float x) {
    float y;
    asm("ex2.approx.f32 %0, %1;" : "=f"(y) : "f"(x));
    return y;
}

// split pair (x,y) into bf16 hi/lo packed regs
__device__ __forceinline__ void split2(float x, float y, uint32_t& hi, uint32_t& lo) {
    __nv_bfloat162 h = __floats2bfloat162_rn(x, y);
    float hx = __bfloat162float(h.x), hy = __bfloat162float(h.y);
    __nv_bfloat162 l = __floats2bfloat162_rn(x - hx, y - hy);
    hi = *(uint32_t*)&h;
    lo = *(uint32_t*)&l;
}

// split pair (x,y) into fp16 hi/lo packed regs
__device__ __forceinline__ void split2h(float x, float y, uint32_t& hi, uint32_t& lo) {
    __half2 h = __floats2half2_rn(x, y);
    float hx = __half2float(__low2half(h)), hy = __half2float(__high2half(h));
    __half2 l = __floats2half2_rn(x - hx, y - hy);
    hi = *(uint32_t*)&h;
    lo = *(uint32_t*)&l;
}

// ===========================================================================
// Conversion kernels
// ===========================================================================
__global__ void conv_splitx(const float* __restrict__ in,
                            __half* __restrict__ hi, __half* __restrict__ lo) {
    int i = (blockIdx.x * 256 + threadIdx.x) * 4;
    float4 v = *(const float4*)(in + i);
    uint32_t h0, l0, h1, l1;
    split2h(v.x, v.y, h0, l0);
    split2h(v.z, v.w, h1, l1);
    *(uint2*)(hi + i) = make_uint2(h0, h1);
    *(uint2*)(lo + i) = make_uint2(l0, l1);
}

// 4 weight matrices [K,N] fp32 -> single fp16, 4 slabs
__global__ void conv_w(const float* __restrict__ W0, const float* __restrict__ W1,
                       const float* __restrict__ W2, const float* __restrict__ W3,
                       __half* __restrict__ w)
{
    const float* W = (blockIdx.y == 0) ? W0 : (blockIdx.y == 1) ? W1
                   : (blockIdx.y == 2) ? W2 : W3;
    size_t base = (size_t)blockIdx.y * DM_ * DM_;
    int i = (blockIdx.x * 256 + threadIdx.x) * 4;
    float4 v = *(const float4*)(W + i);
    __half2 a = __floats2half2_rn(v.x, v.y);
    __half2 b = __floats2half2_rn(v.z, v.w);
    *(uint2*)(w + base + i) = make_uint2(*(uint32_t*)&a, *(uint32_t*)&b);
}

// ===========================================================================
// fp16 2-pass GEMM: C = (A_hi + A_lo) * W_f16.  128x128 tile, BK=32,
// cp.async 2-stage, 2 CTA/SM. B via ldmatrix.trans from [K,N] layout.
// MODE 0: QKV — fused RoPE + bf16-hi/lo split epilogue.
// MODE 1: out-proj, fp32 epilogue.
// ===========================================================================
#define GP      80                    // A smem row pitch
#define TSZA    (128 * GP)            // A tile: 10240 B
#define PITB    272                   // B smem row pitch (128 fp16 + 16B pad)
#define TSZB    (32 * PITB)           // B tile: 8704 B
#define BQ_O    (2 * TSZA)            // 20480
#define STG     (BQ_O + TSZB)         // 29184 per stage
#define G_SMEM  (2 * STG)             // 58368

#define QSCALE  0.1803368801111204f   // 0.125 * log2(e)

template<int MODE>
__global__ __launch_bounds__(256, 2) void gemm128(
    const __half* __restrict__ Ah, const __half* __restrict__ Al,
    const __half* __restrict__ Wp,
    const float* __restrict__ cs, const float* __restrict__ sn,
    float* __restrict__ Cf,
    __nv_bfloat16* __restrict__ qh, __nv_bfloat16* __restrict__ ql,
    __nv_bfloat16* __restrict__ kh, __nv_bfloat16* __restrict__ kl,
    __nv_bfloat16* __restrict__ vh, __nv_bfloat16* __restrict__ vl)
{
    extern __shared__ __align__(16) char sm[];
    const int tid  = threadIdx.x;
    const int wid  = tid >> 5;
    const int lane = tid & 31;
    const int wm   = wid & 3;
    const int wn   = wid >> 2;
    const int widx = (MODE == 0) ? (blockIdx.x >> 3) : 3;
    const int n0   = (blockIdx.x & 7) * 128;
    const int m0   = blockIdx.y * 128;
    const uint32_t sb = smem_u32(sm);

    const __half* gAh = Ah + (size_t)m0 * DM_;
    const __half* gAl = Al + (size_t)m0 * DM_;
    const __half* gW  = Wp + (size_t)widx * DM_ * DM_ + n0;

    const int arow = tid >> 2;         // 0..63
    const int acg  = tid & 3;
    const int brow = tid >> 4;         // 0..15
    const int bcg  = tid & 15;

    #define ISSUE(st_, k0_)                                                    \
        {                                                                      \
            uint32_t dA = sb + (st_) * STG + arow * GP + acg * 16;             \
            const __half* ga = gAh + (size_t)arow * DM_ + (k0_) + acg * 8;     \
            const __half* gl = gAl + (size_t)arow * DM_ + (k0_) + acg * 8;     \
            CP_ASYNC16(dA,                  ga);                               \
            CP_ASYNC16(dA + 64 * GP,        ga + (size_t)64 * DM_);            \
            CP_ASYNC16(dA + TSZA,           gl);                               \
            CP_ASYNC16(dA + TSZA + 64 * GP, gl + (size_t)64 * DM_);            \
            uint32_t dB = sb + (st_) * STG + BQ_O + brow * PITB + bcg * 16;    \
            const __half* gb = gW + (size_t)((k0_) + brow) * DM_ + bcg * 8;    \
            CP_ASYNC16(dB,             gb);                                    \
            CP_ASYNC16(dB + 16 * PITB, gb + (size_t)16 * DM_);                 \
            CP_COMMIT();                                                       \
        }

    const uint32_t a_off = (uint32_t)((lane & 15) * GP + (lane >> 4) * 16);
    const uint32_t b_off = (uint32_t)((lane & 7) * PITB +
                                      ((lane >> 3) & 1) * 8 * PITB + (lane >> 4) * 16);

    float acc[2][8][4];
    #pragma unroll
    for (int i = 0; i < 2; i++)
        #pragma unroll
        for (int j = 0; j < 8; j++)
            #pragma unroll
            for (int l = 0; l < 4; l++) acc[i][j][l] = 0.f;

    ISSUE(0, 0);
    ISSUE(1, 32);

    const int NIT = DM_ / 32;   // 32
    for (int c = 0; c < NIT; c++) {
        if (c + 1 < NIT) { CP_WAIT1(); } else { CP_WAIT0(); }
        __syncthreads();

        const uint32_t stb = sb + (c & 1) * STG;
        #pragma unroll
        for (int ks = 0; ks < 2; ks++) {
            uint32_t ahf[2][4], alf[2][4];
            #pragma unroll
            for (int mt = 0; mt < 2; mt++) {
                uint32_t ab = stb + (uint32_t)((wm * 32 + mt * 16) * GP + ks * 32) + a_off;
                ldsm4(ahf[mt], ab);
                ldsm4(alf[mt], ab + TSZA);
            }
            #pragma unroll
            for (int nt = 0; nt < 4; nt++) {
                uint32_t bb = stb + BQ_O + (uint32_t)(ks * 16 * PITB +
                              wn * 128 + nt * 32) + b_off;
                uint32_t th[4];
                ldsm4t(th, bb);
                #pragma unroll
                for (int mt = 0; mt < 2; mt++) {
                    mma16816h(acc[mt][2*nt],   ahf[mt], th);
                    mma16816h(acc[mt][2*nt],   alf[mt], th);
                    mma16816h(acc[mt][2*nt+1], ahf[mt], th + 2);
                    mma16816h(acc[mt][2*nt+1], alf[mt], th + 2);
                }
            }
        }
        __syncthreads();
        if (c + 2 < NIT) { ISSUE((c & 1), (c + 2) * 32); }
    }

    // ---- epilogue ----
    if (MODE == 1) {
        #pragma unroll
        for (int mt = 0; mt < 2; mt++) {
            int m = m0 + wm * 32 + mt * 16 + (lane >> 2);
            #pragma unroll
            for (int nt = 0; nt < 8; nt++) {
                int n = n0 + wn * 64 + nt * 8 + (lane & 3) * 2;
                *(float2*)(Cf + (size_t)m * DM_ + n) =
                    make_float2(acc[mt][nt][0], acc[mt][nt][1]);
                *(float2*)(Cf + (size_t)(m + 8) * DM_ + n) =
                    make_float2(acc[mt][nt][2], acc[mt][nt][3]);
            }
        }
    } else {
        __nv_bfloat16* dh = (widx == 0) ? qh : (widx == 1) ? kh : vh;
        __nv_bfloat16* dl = (widx == 0) ? ql : (widx == 1) ? kl : vl;
        #pragma unroll
        for (int mt = 0; mt < 2; mt++) {
            int m  = m0 + wm * 32 + mt * 16 + (lane >> 2);
            int t0 = m & (T_ - 1);
            int t1 = (m + 8) & (T_ - 1);
            #pragma unroll
            for (int nt = 0; nt < 8; nt++) {
                int n = n0 + wn * 64 + nt * 8 + (lane & 3) * 2;
                float e0 = acc[mt][nt][0], o0 = acc[mt][nt][1];
                float e1 = acc[mt][nt][2], o1 = acc[mt][nt][3];
                if (widx <= 1) {       // rope on q, k (q also scaled for exp2)
                    int i = (n & 63) >> 1;
                    float c0 = __ldg(cs + t0 * 32 + i), s0 = __ldg(sn + t0 * 32 + i);
                    float c1 = __ldg(cs + t1 * 32 + i), s1 = __ldg(sn + t1 * 32 + i);
                    float sc = (widx == 0) ? QSCALE : 1.f;
                    float a0 = (e0 * c0 - o0 * s0) * sc, b0 = (e0 * s0 + o0 * c0) * sc;
                    float a1 = (e1 * c1 - o1 * s1) * sc, b1 = (e1 * s1 + o1 * c1) * sc;
                    e0 = a0; o0 = b0; e1 = a1; o1 = b1;
                }
                uint32_t h32, l32;
                split2(e0, o0, h32, l32);
                *(uint32_t*)(dh + (size_t)m * DM_ + n) = h32;
                *(uint32_t*)(dl + (size_t)m * DM_ + n) = l32;
                split2(e1, o1, h32, l32);
                *(uint32_t*)(dh + (size_t)(m + 8) * DM_ + n) = h32;
                *(uint32_t*)(dl + (size_t)(m + 8) * DM_ + n) = l32;
            }
        }
    }
    #undef ISSUE
}

// ===========================================================================
// Tensor-core flash attention (bf16 hi/lo split, causal, fixed-base exp2).
// Balanced CTA pairs (15-bx, bx): 34 k-tiles each. Epilogue emits fp16 z.
// ===========================================================================
#define PIT   144
#define KL_O  9216
#define VH_O  18432
#define VL_O  27648
#define AST   36864                 // stage size
#define ATT_SMEM (2 * AST)          // 73728
#define SOFF  26.0f                 // fixed exp2 offset

__global__ __launch_bounds__(256, 2) void attn_mma(
    const __nv_bfloat16* __restrict__ qh, const __nv_bfloat16* __restrict__ ql,
    const __nv_bfloat16* __restrict__ kh, const __nv_bfloat16* __restrict__ kl,
    const __nv_bfloat16* __restrict__ vh, const __nv_bfloat16* __restrict__ vl,
    __half* __restrict__ zh, __half* __restrict__ zl)
{
    extern __shared__ __align__(16) char sm[];
    const int tid  = threadIdx.x;
    const int lane = tid & 31;
    const int wq   = tid >> 5;
    const int bx   = blockIdx.x;          // 0..7
    const int bh_  = blockIdx.y;
    const int b    = bh_ >> 4;
    const int h    = bh_ & 15;
    const int bT   = b * T_;
    const uint32_t sb = smem_u32(sm);
    const size_t hcol = (size_t)h * DH_;

    const uint32_t k_off = ((lane >> 4) * 8 + (lane & 7)) * PIT + ((lane >> 3) & 1) * 16;
    const uint32_t v_off = (lane & 7) * PIT + ((lane >> 3) & 1) * 8 * PIT + (lane >> 4) * 16;

    #define AISSUE(st_, k0_)                                                   \
        {                                                                      \
            int r = tid >> 3, cc = tid & 7;                                    \
            uint32_t d = sb + (st_) * AST + r * PIT + cc * 16;                 \
            size_t g = ((size_t)(bT + (k0_) + r)) * DM_ + hcol + cc * 8;       \
            CP_ASYNC16(d,                   kh + g);                           \
            CP_ASYNC16(d + 32 * PIT,        kh + g + 32 * DM_);                \
            CP_ASYNC16(d + KL_O,            kl + g);                           \
            CP_ASYNC16(d + KL_O + 32 * PIT, kl + g + 32 * DM_);                \
            CP_ASYNC16(d + VH_O,            vh + g);                           \
            CP_ASYNC16(d + VH_O + 32 * PIT, vh + g + 32 * DM_);                \
            CP_ASYNC16(d + VL_O,            vl + g);                           \
            CP_ASYNC16(d + VL_O + 32 * PIT, vl + g + 32 * DM_);                \
            CP_COMMIT();                                                       \
        }

    #pragma unroll 1
    for (int ph = 0; ph < 2; ph++) {
        const int qi = ph ? bx : 15 - bx;     // heavy tile first
        const int q0 = qi * 128;
        const int nkt = 2 * qi + 2;
        const int qg_lo = q0 + wq * 16 + (lane >> 2);
        const int qg_hi = qg_lo + 8;

        // ---- stage Q (hi/lo) through smem, extract A-fragments ----
        {
            int r = tid >> 3, c = tid & 7;
            #pragma unroll
            for (int i = 0; i < 4; i++) {
                int row = r + i * 32;
                size_t g = ((size_t)(bT + q0 + row)) * DM_ + hcol + c * 8;
                *(uint4*)(sm + row * PIT + c * 16)         = *(const uint4*)(qh + g);
                *(uint4*)(sm + 18432 + row * PIT + c * 16) = *(const uint4*)(ql + g);
            }
        }
        __syncthreads();

        uint32_t qfh[4][4], qfl[4][4];
        {
            const uint32_t a_off = (lane & 15) * PIT + (lane >> 4) * 16;
            #pragma unroll
            for (int ks = 0; ks < 4; ks++) {
                ldsm4(qfh[ks], sb + (wq * 16) * PIT + ks * 32 + a_off);
                ldsm4(qfl[ks], sb + 18432 + (wq * 16) * PIT + ks * 32 + a_off);
            }
        }
        __syncthreads();   // Q reads done; smem reusable for K/V stages

        AISSUE(0, 0);
        if (nkt > 1) AISSUE(1, 64);

        float o[8][4];
        #pragma unroll
        for (int i = 0; i < 8; i++)
            #pragma unroll
            for (int j = 0; j < 4; j++) o[i][j] = 0.f;
        float l_lo = 0.f, l_hi = 0.f;

        for (int kt = 0; kt < nkt; kt++) {
            const int k0 = kt * 64;
            if (kt + 1 < nkt) { CP_WAIT1(); } else { CP_WAIT0(); }
            __syncthreads();
            const uint32_t stb = sb + (kt & 1) * AST;

            // ---- S' = Q' K^T (3-pass split) ----
            float sf[8][4];
            #pragma unroll
            for (int i = 0; i < 8; i++)
                #pragma unroll
                for (int j = 0; j < 4; j++) sf[i][j] = 0.f;

            #pragma unroll
            for (int ks = 0; ks < 4; ks++) {
                #pragma unroll
                for (int nt2 = 0; nt2 < 4; nt2++) {
                    uint32_t th[4], tl[4];
                    ldsm4(th, stb + (nt2 * 16) * PIT + ks * 32 + k_off);
                    ldsm4(tl, stb + KL_O + (nt2 * 16) * PIT + ks * 32 + k_off);
                    mma16816(sf[2*nt2],   qfh[ks], th);
                    mma16816(sf[2*nt2],   qfh[ks], tl);
                    mma16816(sf[2*nt2],   qfl[ks], th);
                    mma16816(sf[2*nt2+1], qfh[ks], th + 2);
                    mma16816(sf[2*nt2+1], qfh[ks], tl + 2);
                    mma16816(sf[2*nt2+1], qfl[ks], th + 2);
                }
            }

            if (kt >= nkt - 2) {
                #pragma unroll
                for (int nt = 0; nt < 8; nt++) {
                    int kg = k0 + nt * 8 + (lane & 3) * 2;
                    if (kg     > qg_lo) sf[nt][0] = -1e30f;
                    if (kg + 1 > qg_lo) sf[nt][1] = -1e30f;
                    if (kg     > qg_hi) sf[nt][2] = -1e30f;
                    if (kg + 1 > qg_hi) sf[nt][3] = -1e30f;
                }
            }

            // ---- p = 2^(s' - 26); accumulate l per-thread ----
            #pragma unroll
            for (int nt = 0; nt < 8; nt++) {
                sf[nt][0] = ex2f(sf[nt][0] - SOFF);
                sf[nt][1] = ex2f(sf[nt][1] - SOFF);
                sf[nt][2] = ex2f(sf[nt][2] - SOFF);
                sf[nt][3] = ex2f(sf[nt][3] - SOFF);
                l_lo += sf[nt][0] + sf[nt][1];
                l_hi += sf[nt][2] + sf[nt][3];
            }

            // ---- O += P V (pack P per-j to keep registers low) ----
            #pragma unroll
            for (int j = 0; j < 4; j++) {
                uint32_t pfh[4], pfl[4];
                split2(sf[2*j][0],   sf[2*j][1],   pfh[0], pfl[0]);
                split2(sf[2*j][2],   sf[2*j][3],   pfh[1], pfl[1]);
                split2(sf[2*j+1][0], sf[2*j+1][1], pfh[2], pfl[2]);
                split2(sf[2*j+1][2], sf[2*j+1][3], pfh[3], pfl[3]);
                #pragma unroll
                for (int d2 = 0; d2 < 4; d2++) {
                    uint32_t th[4], tl[4];
                    ldsm4t(th, stb + VH_O + (j * 16) * PIT + d2 * 32 + v_off);
                    ldsm4t(tl, stb + VL_O + (j * 16) * PIT + d2 * 32 + v_off);
                    mma16816(o[2*d2],   pfh, th);
                    mma16816(o[2*d2],   pfh, tl);
                    mma16816(o[2*d2],   pfl, th);
                    mma16816(o[2*d2+1], pfh, th + 2);
                    mma16816(o[2*d2+1], pfh, tl + 2);
                    mma16816(o[2*d2+1], pfl, th + 2);
                }
            }

            __syncthreads();
            if (kt + 2 < nkt) { AISSUE((kt & 1), (kt + 2) * 64); }
        }

        // ---- epilogue: reduce l across quad lanes, normalize, write fp16 z ----
        l_lo += __shfl_xor_sync(0xffffffffu, l_lo, 1);
        l_lo += __shfl_xor_sync(0xffffffffu, l_lo, 2);
        l_hi += __shfl_xor_sync(0xffffffffu, l_hi, 1);
        l_hi += __shfl_xor_sync(0xffffffffu, l_hi, 2);
        float il_lo = 1.f / l_lo, il_hi = 1.f / l_hi;
        size_t out_lo = ((size_t)(bT + qg_lo)) * DM_ + hcol + (lane & 3) * 2;
        #pragma unroll
        for (int nt = 0; nt < 8; nt++) {
            uint32_t h32, l32;
            split2h(o[nt][0] * il_lo, o[nt][1] * il_lo, h32, l32);
            *(uint32_t*)(zh + out_lo + nt * 8) = h32;
            *(uint32_t*)(zl + out_lo + nt * 8) = l32;
            split2h(o[nt][2] * il_hi, o[nt][3] * il_hi, h32, l32);
            *(uint32_t*)(zh + out_lo + 8 * DM_ + nt * 8) = h32;
            *(uint32_t*)(zl + out_lo + 8 * DM_ + nt * 8) = l32;
        }
    }
    #undef AISSUE
}

// ---------------------------------------------------------------------------
extern "C" void kernel_launch(void* const* d_in, const int* in_sizes, int n_in,
                              void* d_out, int out_size)
{
    const float* x  = (const float*)d_in[0];
    const float* cs = (const float*)d_in[1];
    const float* sn = (const float*)d_in[2];
    const float* Wq = (const float*)d_in[3];
    const float* Wk = (const float*)d_in[4];
    const float* Wv = (const float*)d_in[5];
    const float* Wo = (const float*)d_in[6];
    float* out = (float*)d_out;

    __half *ahp, *alp, *wp, *zhp, *zlp;
    __nv_bfloat16 *qhp, *qlp, *khp, *klp, *vhp, *vlp;
    cudaGetSymbolAddress((void**)&ahp, g_ah);
    cudaGetSymbolAddress((void**)&alp, g_al);
    cudaGetSymbolAddress((void**)&wp, g_w);
    cudaGetSymbolAddress((void**)&qhp, g_qh);
    cudaGetSymbolAddress((void**)&qlp, g_ql);
    cudaGetSymbolAddress((void**)&khp, g_kh);
    cudaGetSymbolAddress((void**)&klp, g_kl);
    cudaGetSymbolAddress((void**)&vhp, g_vh);
    cudaGetSymbolAddress((void**)&vlp, g_vl);
    cudaGetSymbolAddress((void**)&zhp, g_zh);
    cudaGetSymbolAddress((void**)&zlp, g_zl);

    cudaFuncSetAttribute(gemm128<0>, cudaFuncAttributeMaxDynamicSharedMemorySize, G_SMEM);
    cudaFuncSetAttribute(gemm128<1>, cudaFuncAttributeMaxDynamicSharedMemorySize, G_SMEM);
    cudaFuncSetAttribute(attn_mma, cudaFuncAttributeMaxDynamicSharedMemorySize, ATT_SMEM);

    // elementwise splits: x -> fp16 hi/lo, W -> single fp16 (4 slabs)
    conv_splitx<<<BT_ * DM_ / 1024, 256>>>(x, ahp, alp);
    conv_w<<<dim3(DM_ * DM_ / 1024, 4), 256>>>(Wq, Wk, Wv, Wo, wp);

    // fused QKV GEMM + RoPE + bf16-split epilogue
    gemm128<0><<<dim3(24, BT_ / 128), 256, G_SMEM>>>(
        ahp, alp, wp, cs, sn, nullptr,
        qhp, qlp, khp, klp, vhp, vlp);

    attn_mma<<<dim3(8, B_ * H_), 256, ATT_SMEM>>>(qhp, qlp, khp, klp,
                                                  vhp, vlp, zhp, zlp);

    // out = z Wo
    gemm128<1><<<dim3(8, BT_ / 128), 256, G_SMEM>>>(
        zhp, zlp, wp, cs, sn, out,
        nullptr, nullptr, nullptr, nullptr, nullptr, nullptr);
}

// round 10
// speedup vs baseline: 1.6311x; 1.1549x over previous
#include <cuda_runtime.h>
#include <cuda_bf16.h>
#include <cuda_fp16.h>
#include <cstdint>

#define B_   2
#define T_   2048
#define DM_  1024
#define H_   16
#define DH_  64
#define BT_  (B_ * T_)   // 4096

// Scratch (allocation-free rule: device globals)
__device__ __half g_ah[BT_ * DM_], g_al[BT_ * DM_];   // x hi/lo (fp16)
__device__ __half g_w[4 * DM_ * DM_];                 // W single fp16, [K,N], 4 slabs
__device__ __half g_qh[BT_ * DM_], g_ql[BT_ * DM_];   // q hi/lo (fp16)
__device__ __half g_k[BT_ * DM_];                     // k single fp16
__device__ __half g_v[BT_ * DM_];                     // v single fp16
__device__ __half g_zh[BT_ * DM_], g_zl[BT_ * DM_];   // z hi/lo (fp16)

// ===========================================================================
// Warp-MMA + cp.async helpers (baseline PTX — no tcgen05 on this harness)
// ===========================================================================
__device__ __forceinline__ uint32_t smem_u32(const void* p) {
    uint32_t a;
    asm("{ .reg .u64 t; cvta.to.shared.u64 t, %1; cvt.u32.u64 %0, t; }"
        : "=r"(a) : "l"(p));
    return a;
}

__device__ __forceinline__ void ldsm4(uint32_t* r, uint32_t addr) {
    asm volatile("ldmatrix.sync.aligned.m8n8.x4.shared.b16 {%0,%1,%2,%3}, [%4];"
                 : "=r"(r[0]), "=r"(r[1]), "=r"(r[2]), "=r"(r[3]) : "r"(addr));
}
__device__ __forceinline__ void ldsm4t(uint32_t* r, uint32_t addr) {
    asm volatile("ldmatrix.sync.aligned.m8n8.x4.trans.shared.b16 {%0,%1,%2,%3}, [%4];"
                 : "=r"(r[0]), "=r"(r[1]), "=r"(r[2]), "=r"(r[3]) : "r"(addr));
}

// fp16 MMA
__device__ __forceinline__ void mma16816h(float* c, const uint32_t* a,
                                          const uint32_t* b) {
    asm volatile(
        "mma.sync.aligned.m16n8k16.row.col.f32.f16.f16.f32 "
        "{%0,%1,%2,%3}, {%4,%5,%6,%7}, {%8,%9}, {%0,%1,%2,%3};"
        : "+f"(c[0]), "+f"(c[1]), "+f"(c[2]), "+f"(c[3])
        : "r"(a[0]), "r"(a[1]), "r"(a[2]), "r"(a[3]), "r"(b[0]), "r"(b[1]));
}

#define CP_ASYNC16(dst, src) \
    asm volatile("cp.async.cg.shared.global [%0], [%1], 16;" :: "r"(dst), "l"(src))
#define CP_COMMIT() asm volatile("cp.async.commit_group;")
#define CP_WAIT1()  asm volatile("cp.async.wait_group 1;")
#define CP_WAIT0()  asm volatile("cp.async.wait_group 0;")

__device__ __forceinline__ float ex2f(float x) {
    float y;
    asm("ex2.approx.f32 %0, %1;" : "=f"(y) : "f"(x));
    return y;
}

// split pair (x,y) into fp16 hi/lo packed regs
__device__ __forceinline__ void split2h(float x, float y, uint32_t& hi, uint32_t& lo) {
    __half2 h = __floats2half2_rn(x, y);
    float hx = __half2float(__low2half(h)), hy = __half2float(__high2half(h));
    __half2 l = __floats2half2_rn(x - hx, y - hy);
    hi = *(uint32_t*)&h;
    lo = *(uint32_t*)&l;
}

// ===========================================================================
// Conversion kernels
// ===========================================================================
__global__ void conv_splitx(const float* __restrict__ in,
                            __half* __restrict__ hi, __half* __restrict__ lo) {
    int i = (blockIdx.x * 256 + threadIdx.x) * 4;
    float4 v = *(const float4*)(in + i);
    uint32_t h0, l0, h1, l1;
    split2h(v.x, v.y, h0, l0);
    split2h(v.z, v.w, h1, l1);
    *(uint2*)(hi + i) = make_uint2(h0, h1);
    *(uint2*)(lo + i) = make_uint2(l0, l1);
}

// 4 weight matrices [K,N] fp32 -> single fp16, 4 slabs
__global__ void conv_w(const float* __restrict__ W0, const float* __restrict__ W1,
                       const float* __restrict__ W2, const float* __restrict__ W3,
                       __half* __restrict__ w)
{
    const float* W = (blockIdx.y == 0) ? W0 : (blockIdx.y == 1) ? W1
                   : (blockIdx.y == 2) ? W2 : W3;
    size_t base = (size_t)blockIdx.y * DM_ * DM_;
    int i = (blockIdx.x * 256 + threadIdx.x) * 4;
    float4 v = *(const float4*)(W + i);
    __half2 a = __floats2half2_rn(v.x, v.y);
    __half2 b = __floats2half2_rn(v.z, v.w);
    *(uint2*)(w + base + i) = make_uint2(*(uint32_t*)&a, *(uint32_t*)&b);
}

// ===========================================================================
// fp16 2-pass GEMM: C = (A_hi + A_lo) * W_f16.  128x128 tile, BK=32,
// cp.async 2-stage, 2 CTA/SM. B via ldmatrix.trans from [K,N] layout.
// MODE 0: QKV — RoPE epilogue; q -> fp16 hi/lo, k/v -> single fp16.
// MODE 1: out-proj, fp32 epilogue.
// ===========================================================================
#define GP      80                    // A smem row pitch
#define TSZA    (128 * GP)            // A tile: 10240 B
#define PITB    272                   // B smem row pitch (128 fp16 + 16B pad)
#define TSZB    (32 * PITB)           // B tile: 8704 B
#define BQ_O    (2 * TSZA)            // 20480
#define STG     (BQ_O + TSZB)         // 29184 per stage
#define G_SMEM  (2 * STG)             // 58368

#define QSCALE  0.1803368801111204f   // 0.125 * log2(e)

template<int MODE>
__global__ __launch_bounds__(256, 2) void gemm128(
    const __half* __restrict__ Ah, const __half* __restrict__ Al,
    const __half* __restrict__ Wp,
    const float* __restrict__ cs, const float* __restrict__ sn,
    float* __restrict__ Cf,
    __half* __restrict__ qh, __half* __restrict__ ql,
    __half* __restrict__ kq, __half* __restrict__ vq)
{
    extern __shared__ __align__(16) char sm[];
    const int tid  = threadIdx.x;
    const int wid  = tid >> 5;
    const int lane = tid & 31;
    const int wm   = wid & 3;
    const int wn   = wid >> 2;
    const int widx = (MODE == 0) ? (blockIdx.x >> 3) : 3;
    const int n0   = (blockIdx.x & 7) * 128;
    const int m0   = blockIdx.y * 128;
    const uint32_t sb = smem_u32(sm);

    const __half* gAh = Ah + (size_t)m0 * DM_;
    const __half* gAl = Al + (size_t)m0 * DM_;
    const __half* gW  = Wp + (size_t)widx * DM_ * DM_ + n0;

    const int arow = tid >> 2;         // 0..63
    const int acg  = tid & 3;
    const int brow = tid >> 4;         // 0..15
    const int bcg  = tid & 15;

    #define ISSUE(st_, k0_)                                                    \
        {                                                                      \
            uint32_t dA = sb + (st_) * STG + arow * GP + acg * 16;             \
            const __half* ga = gAh + (size_t)arow * DM_ + (k0_) + acg * 8;     \
            const __half* gl = gAl + (size_t)arow * DM_ + (k0_) + acg * 8;     \
            CP_ASYNC16(dA,                  ga);                               \
            CP_ASYNC16(dA + 64 * GP,        ga + (size_t)64 * DM_);            \
            CP_ASYNC16(dA + TSZA,           gl);                               \
            CP_ASYNC16(dA + TSZA + 64 * GP, gl + (size_t)64 * DM_);            \
            uint32_t dB = sb + (st_) * STG + BQ_O + brow * PITB + bcg * 16;    \
            const __half* gb = gW + (size_t)((k0_) + brow) * DM_ + bcg * 8;    \
            CP_ASYNC16(dB,             gb);                                    \
            CP_ASYNC16(dB + 16 * PITB, gb + (size_t)16 * DM_);                 \
            CP_COMMIT();                                                       \
        }

    const uint32_t a_off = (uint32_t)((lane & 15) * GP + (lane >> 4) * 16);
    const uint32_t b_off = (uint32_t)((lane & 7) * PITB +
                                      ((lane >> 3) & 1) * 8 * PITB + (lane >> 4) * 16);

    float acc[2][8][4];
    #pragma unroll
    for (int i = 0; i < 2; i++)
        #pragma unroll
        for (int j = 0; j < 8; j++)
            #pragma unroll
            for (int l = 0; l < 4; l++) acc[i][j][l] = 0.f;

    ISSUE(0, 0);
    ISSUE(1, 32);

    const int NIT = DM_ / 32;   // 32
    for (int c = 0; c < NIT; c++) {
        if (c + 1 < NIT) { CP_WAIT1(); } else { CP_WAIT0(); }
        __syncthreads();

        const uint32_t stb = sb + (c & 1) * STG;
        #pragma unroll
        for (int ks = 0; ks < 2; ks++) {
            uint32_t ahf[2][4], alf[2][4];
            #pragma unroll
            for (int mt = 0; mt < 2; mt++) {
                uint32_t ab = stb + (uint32_t)((wm * 32 + mt * 16) * GP + ks * 32) + a_off;
                ldsm4(ahf[mt], ab);
                ldsm4(alf[mt], ab + TSZA);
            }
            #pragma unroll
            for (int nt = 0; nt < 4; nt++) {
                uint32_t bb = stb + BQ_O + (uint32_t)(ks * 16 * PITB +
                              wn * 128 + nt * 32) + b_off;
                uint32_t th[4];
                ldsm4t(th, bb);
                #pragma unroll
                for (int mt = 0; mt < 2; mt++) {
                    mma16816h(acc[mt][2*nt],   ahf[mt], th);
                    mma16816h(acc[mt][2*nt],   alf[mt], th);
                    mma16816h(acc[mt][2*nt+1], ahf[mt], th + 2);
                    mma16816h(acc[mt][2*nt+1], alf[mt], th + 2);
                }
            }
        }
        __syncthreads();
        if (c + 2 < NIT) { ISSUE((c & 1), (c + 2) * 32); }
    }

    // ---- epilogue ----
    if (MODE == 1) {
        #pragma unroll
        for (int mt = 0; mt < 2; mt++) {
            int m = m0 + wm * 32 + mt * 16 + (lane >> 2);
            #pragma unroll
            for (int nt = 0; nt < 8; nt++) {
                int n = n0 + wn * 64 + nt * 8 + (lane & 3) * 2;
                *(float2*)(Cf + (size_t)m * DM_ + n) =
                    make_float2(acc[mt][nt][0], acc[mt][nt][1]);
                *(float2*)(Cf + (size_t)(m + 8) * DM_ + n) =
                    make_float2(acc[mt][nt][2], acc[mt][nt][3]);
            }
        }
    } else {
        #pragma unroll
        for (int mt = 0; mt < 2; mt++) {
            int m  = m0 + wm * 32 + mt * 16 + (lane >> 2);
            int t0 = m & (T_ - 1);
            int t1 = (m + 8) & (T_ - 1);
            #pragma unroll
            for (int nt = 0; nt < 8; nt++) {
                int n = n0 + wn * 64 + nt * 8 + (lane & 3) * 2;
                float e0 = acc[mt][nt][0], o0 = acc[mt][nt][1];
                float e1 = acc[mt][nt][2], o1 = acc[mt][nt][3];
                if (widx <= 1) {       // rope on q, k (q also scaled for exp2)
                    int i = (n & 63) >> 1;
                    float c0 = __ldg(cs + t0 * 32 + i), s0 = __ldg(sn + t0 * 32 + i);
                    float c1 = __ldg(cs + t1 * 32 + i), s1 = __ldg(sn + t1 * 32 + i);
                    float sc = (widx == 0) ? QSCALE : 1.f;
                    float a0 = (e0 * c0 - o0 * s0) * sc, b0 = (e0 * s0 + o0 * c0) * sc;
                    float a1 = (e1 * c1 - o1 * s1) * sc, b1 = (e1 * s1 + o1 * c1) * sc;
                    e0 = a0; o0 = b0; e1 = a1; o1 = b1;
                }
                if (widx == 0) {        // q: fp16 hi/lo
                    uint32_t h32, l32;
                    split2h(e0, o0, h32, l32);
                    *(uint32_t*)(qh + (size_t)m * DM_ + n) = h32;
                    *(uint32_t*)(ql + (size_t)m * DM_ + n) = l32;
                    split2h(e1, o1, h32, l32);
                    *(uint32_t*)(qh + (size_t)(m + 8) * DM_ + n) = h32;
                    *(uint32_t*)(ql + (size_t)(m + 8) * DM_ + n) = l32;
                } else {                // k, v: single fp16
                    __half* d = (widx == 1) ? kq : vq;
                    __half2 p0 = __floats2half2_rn(e0, o0);
                    __half2 p1 = __floats2half2_rn(e1, o1);
                    *(uint32_t*)(d + (size_t)m * DM_ + n)       = *(uint32_t*)&p0;
                    *(uint32_t*)(d + (size_t)(m + 8) * DM_ + n) = *(uint32_t*)&p1;
                }
            }
        }
    }
    #undef ISSUE
}

// ===========================================================================
// Tensor-core flash attention (fp16 2-pass, causal, fixed-base exp2 SOFF=0).
// QK: (q_hi + q_lo) · k_f16 ; PV: (p_hi + p_lo) · v_f16.
// |s'| <= ||q'||*||k|| ~ 13 => p in [2^-13, 2^13], inside fp16 normal range.
// Balanced CTA pairs (15-bx, bx): 34 k-tiles each; 2 CTA/SM.
// ===========================================================================
#define PIT   144
#define V_O   9216                  // V tile offset within stage
#define AST   18432                 // stage size (K + V single tiles)
#define ATT_SMEM (2 * AST)          // 36864

__global__ __launch_bounds__(256, 2) void attn_mma(
    const __half* __restrict__ qh, const __half* __restrict__ ql,
    const __half* __restrict__ kq, const __half* __restrict__ vq,
    __half* __restrict__ zh, __half* __restrict__ zl)
{
    extern __shared__ __align__(16) char sm[];
    const int tid  = threadIdx.x;
    const int lane = tid & 31;
    const int wq   = tid >> 5;
    const int bx   = blockIdx.x;          // 0..7
    const int bh_  = blockIdx.y;
    const int b    = bh_ >> 4;
    const int h    = bh_ & 15;
    const int bT   = b * T_;
    const uint32_t sb = smem_u32(sm);
    const size_t hcol = (size_t)h * DH_;

    const uint32_t k_off = ((lane >> 4) * 8 + (lane & 7)) * PIT + ((lane >> 3) & 1) * 16;
    const uint32_t v_off = (lane & 7) * PIT + ((lane >> 3) & 1) * 8 * PIT + (lane >> 4) * 16;

    #define AISSUE(st_, k0_)                                                   \
        {                                                                      \
            int r = tid >> 3, cc = tid & 7;                                    \
            uint32_t d = sb + (st_) * AST + r * PIT + cc * 16;                 \
            size_t g = ((size_t)(bT + (k0_) + r)) * DM_ + hcol + cc * 8;       \
            CP_ASYNC16(d,                  kq + g);                            \
            CP_ASYNC16(d + 32 * PIT,       kq + g + 32 * DM_);                 \
            CP_ASYNC16(d + V_O,            vq + g);                            \
            CP_ASYNC16(d + V_O + 32 * PIT, vq + g + 32 * DM_);                 \
            CP_COMMIT();                                                       \
        }

    #pragma unroll 1
    for (int ph = 0; ph < 2; ph++) {
        const int qi = ph ? bx : 15 - bx;     // heavy tile first
        const int q0 = qi * 128;
        const int nkt = 2 * qi + 2;
        const int qg_lo = q0 + wq * 16 + (lane >> 2);
        const int qg_hi = qg_lo + 8;

        // ---- stage Q (hi/lo) through smem, extract A-fragments ----
        {
            int r = tid >> 3, c = tid & 7;
            #pragma unroll
            for (int i = 0; i < 4; i++) {
                int row = r + i * 32;
                size_t g = ((size_t)(bT + q0 + row)) * DM_ + hcol + c * 8;
                *(uint4*)(sm + row * PIT + c * 16)         = *(const uint4*)(qh + g);
                *(uint4*)(sm + 18432 + row * PIT + c * 16) = *(const uint4*)(ql + g);
            }
        }
        __syncthreads();

        uint32_t qfh[4][4], qfl[4][4];
        {
            const uint32_t a_off = (lane & 15) * PIT + (lane >> 4) * 16;
            #pragma unroll
            for (int ks = 0; ks < 4; ks++) {
                ldsm4(qfh[ks], sb + (wq * 16) * PIT + ks * 32 + a_off);
                ldsm4(qfl[ks], sb + 18432 + (wq * 16) * PIT + ks * 32 + a_off);
            }
        }
        __syncthreads();   // Q reads done; smem reusable for K/V stages

        AISSUE(0, 0);
        if (nkt > 1) AISSUE(1, 64);

        float o[8][4];
        #pragma unroll
        for (int i = 0; i < 8; i++)
            #pragma unroll
            for (int j = 0; j < 4; j++) o[i][j] = 0.f;
        float l_lo = 0.f, l_hi = 0.f;

        for (int kt = 0; kt < nkt; kt++) {
            const int k0 = kt * 64;
            if (kt + 1 < nkt) { CP_WAIT1(); } else { CP_WAIT0(); }
            __syncthreads();
            const uint32_t stb = sb + (kt & 1) * AST;

            // ---- S' = Q' K^T (2-pass: q_hi, q_lo vs single K) ----
            float sf[8][4];
            #pragma unroll
            for (int i = 0; i < 8; i++)
                #pragma unroll
                for (int j = 0; j < 4; j++) sf[i][j] = 0.f;

            #pragma unroll
            for (int ks = 0; ks < 4; ks++) {
                #pragma unroll
                for (int nt2 = 0; nt2 < 4; nt2++) {
                    uint32_t th[4];
                    ldsm4(th, stb + (nt2 * 16) * PIT + ks * 32 + k_off);
                    mma16816h(sf[2*nt2],   qfh[ks], th);
                    mma16816h(sf[2*nt2],   qfl[ks], th);
                    mma16816h(sf[2*nt2+1], qfh[ks], th + 2);
                    mma16816h(sf[2*nt2+1], qfl[ks], th + 2);
                }
            }

            if (kt >= nkt - 2) {
                #pragma unroll
                for (int nt = 0; nt < 8; nt++) {
                    int kg = k0 + nt * 8 + (lane & 3) * 2;
                    if (kg     > qg_lo) sf[nt][0] = -1e30f;
                    if (kg + 1 > qg_lo) sf[nt][1] = -1e30f;
                    if (kg     > qg_hi) sf[nt][2] = -1e30f;
                    if (kg + 1 > qg_hi) sf[nt][3] = -1e30f;
                }
            }

            // ---- p = 2^s' (SOFF=0; |s'|<=~13 fits fp16); accumulate l ----
            #pragma unroll
            for (int nt = 0; nt < 8; nt++) {
                sf[nt][0] = ex2f(sf[nt][0]);
                sf[nt][1] = ex2f(sf[nt][1]);
                sf[nt][2] = ex2f(sf[nt][2]);
                sf[nt][3] = ex2f(sf[nt][3]);
                l_lo += sf[nt][0] + sf[nt][1];
                l_hi += sf[nt][2] + sf[nt][3];
            }

            // ---- O += P V (P hi/lo vs single V) ----
            #pragma unroll
            for (int j = 0; j < 4; j++) {
                uint32_t pfh[4], pfl[4];
                split2h(sf[2*j][0],   sf[2*j][1],   pfh[0], pfl[0]);
                split2h(sf[2*j][2],   sf[2*j][3],   pfh[1], pfl[1]);
                split2h(sf[2*j+1][0], sf[2*j+1][1], pfh[2], pfl[2]);
                split2h(sf[2*j+1][2], sf[2*j+1][3], pfh[3], pfl[3]);
                #pragma unroll
                for (int d2 = 0; d2 < 4; d2++) {
                    uint32_t th[4];
                    ldsm4t(th, stb + V_O + (j * 16) * PIT + d2 * 32 + v_off);
                    mma16816h(o[2*d2],   pfh, th);
                    mma16816h(o[2*d2],   pfl, th);
                    mma16816h(o[2*d2+1], pfh, th + 2);
                    mma16816h(o[2*d2+1], pfl, th + 2);
                }
            }

            __syncthreads();
            if (kt + 2 < nkt) { AISSUE((kt & 1), (kt + 2) * 64); }
        }

        // ---- epilogue: reduce l across quad lanes, normalize, write fp16 z ----
        l_lo += __shfl_xor_sync(0xffffffffu, l_lo, 1);
        l_lo += __shfl_xor_sync(0xffffffffu, l_lo, 2);
        l_hi += __shfl_xor_sync(0xffffffffu, l_hi, 1);
        l_hi += __shfl_xor_sync(0xffffffffu, l_hi, 2);
        float il_lo = 1.f / l_lo, il_hi = 1.f / l_hi;
        size_t out_lo = ((size_t)(bT + qg_lo)) * DM_ + hcol + (lane & 3) * 2;
        #pragma unroll
        for (int nt = 0; nt < 8; nt++) {
            uint32_t h32, l32;
            split2h(o[nt][0] * il_lo, o[nt][1] * il_lo, h32, l32);
            *(uint32_t*)(zh + out_lo + nt * 8) = h32;
            *(uint32_t*)(zl + out_lo + nt * 8) = l32;
            split2h(o[nt][2] * il_hi, o[nt][3] * il_hi, h32, l32);
            *(uint32_t*)(zh + out_lo + 8 * DM_ + nt * 8) = h32;
            *(uint32_t*)(zl + out_lo + 8 * DM_ + nt * 8) = l32;
        }
    }
    #undef AISSUE
}

// ---------------------------------------------------------------------------
extern "C" void kernel_launch(void* const* d_in, const int* in_sizes, int n_in,
                              void* d_out, int out_size)
{
    const float* x  = (const float*)d_in[0];
    const float* cs = (const float*)d_in[1];
    const float* sn = (const float*)d_in[2];
    const float* Wq = (const float*)d_in[3];
    const float* Wk = (const float*)d_in[4];
    const float* Wv = (const float*)d_in[5];
    const float* Wo = (const float*)d_in[6];
    float* out = (float*)d_out;

    __half *ahp, *alp, *wp, *qhp, *qlp, *kp, *vp, *zhp, *zlp;
    cudaGetSymbolAddress((void**)&ahp, g_ah);
    cudaGetSymbolAddress((void**)&alp, g_al);
    cudaGetSymbolAddress((void**)&wp, g_w);
    cudaGetSymbolAddress((void**)&qhp, g_qh);
    cudaGetSymbolAddress((void**)&qlp, g_ql);
    cudaGetSymbolAddress((void**)&kp, g_k);
    cudaGetSymbolAddress((void**)&vp, g_v);
    cudaGetSymbolAddress((void**)&zhp, g_zh);
    cudaGetSymbolAddress((void**)&zlp, g_zl);

    cudaFuncSetAttribute(gemm128<0>, cudaFuncAttributeMaxDynamicSharedMemorySize, G_SMEM);
    cudaFuncSetAttribute(gemm128<1>, cudaFuncAttributeMaxDynamicSharedMemorySize, G_SMEM);
    cudaFuncSetAttribute(attn_mma, cudaFuncAttributeMaxDynamicSharedMemorySize, ATT_SMEM);

    // elementwise splits: x -> fp16 hi/lo, W -> single fp16 (4 slabs)
    conv_splitx<<<BT_ * DM_ / 1024, 256>>>(x, ahp, alp);
    conv_w<<<dim3(DM_ * DM_ / 1024, 4), 256>>>(Wq, Wk, Wv, Wo, wp);

    // fused QKV GEMM + RoPE epilogue (q hi/lo, k/v single fp16)
    gemm128<0><<<dim3(24, BT_ / 128), 256, G_SMEM>>>(
        ahp, alp, wp, cs, sn, nullptr, qhp, qlp, kp, vp);

    attn_mma<<<dim3(8, B_ * H_), 256, ATT_SMEM>>>(qhp, qlp, kp, vp, zhp, zlp);

    // out = z Wo
    gemm128<1><<<dim3(8, BT_ / 128), 256, G_SMEM>>>(
        zhp, zlp, wp, cs, sn, out, nullptr, nullptr, nullptr, nullptr);
}

// round 11
// speedup vs baseline: 2.6629x; 1.6325x over previous
#include <cuda_runtime.h>
#include <cuda_fp16.h>
#include <cstdint>

#define B_   2
#define T_   2048
#define DM_  1024
#define H_   16
#define DH_  64
#define BT_  (B_ * T_)   // 4096

// Scratch (allocation-free rule: device globals) — all single fp16 now
__device__ __half g_x[BT_ * DM_];                     // x fp16
__device__ __half g_w[4 * DM_ * DM_];                 // W fp16, [K,N], 4 slabs
__device__ __half g_q[BT_ * DM_];                     // q (rope+scaled)
__device__ __half g_k[BT_ * DM_];                     // k (rope)
__device__ __half g_v[BT_ * DM_];                     // v
__device__ __half g_z[BT_ * DM_];                     // attention output

// ===========================================================================
// Warp-MMA + cp.async helpers (baseline PTX — no tcgen05 on this harness)
// ===========================================================================
__device__ __forceinline__ uint32_t smem_u32(const void* p) {
    uint32_t a;
    asm("{ .reg .u64 t; cvta.to.shared.u64 t, %1; cvt.u32.u64 %0, t; }"
        : "=r"(a) : "l"(p));
    return a;
}

__device__ __forceinline__ void ldsm4(uint32_t* r, uint32_t addr) {
    asm volatile("ldmatrix.sync.aligned.m8n8.x4.shared.b16 {%0,%1,%2,%3}, [%4];"
                 : "=r"(r[0]), "=r"(r[1]), "=r"(r[2]), "=r"(r[3]) : "r"(addr));
}
__device__ __forceinline__ void ldsm4t(uint32_t* r, uint32_t addr) {
    asm volatile("ldmatrix.sync.aligned.m8n8.x4.trans.shared.b16 {%0,%1,%2,%3}, [%4];"
                 : "=r"(r[0]), "=r"(r[1]), "=r"(r[2]), "=r"(r[3]) : "r"(addr));
}

__device__ __forceinline__ void mma16816h(float* c, const uint32_t* a,
                                          const uint32_t* b) {
    asm volatile(
        "mma.sync.aligned.m16n8k16.row.col.f32.f16.f16.f32 "
        "{%0,%1,%2,%3}, {%4,%5,%6,%7}, {%8,%9}, {%0,%1,%2,%3};"
        : "+f"(c[0]), "+f"(c[1]), "+f"(c[2]), "+f"(c[3])
        : "r"(a[0]), "r"(a[1]), "r"(a[2]), "r"(a[3]), "r"(b[0]), "r"(b[1]));
}

#define CP_ASYNC16(dst, src) \
    asm volatile("cp.async.cg.shared.global [%0], [%1], 16;" :: "r"(dst), "l"(src))
#define CP_COMMIT() asm volatile("cp.async.commit_group;")
#define CP_WAIT1()  asm volatile("cp.async.wait_group 1;")
#define CP_WAIT0()  asm volatile("cp.async.wait_group 0;")

__device__ __forceinline__ float ex2f(float x) {
    float y;
    asm("ex2.approx.f32 %0, %1;" : "=f"(y) : "f"(x));
    return y;
}

__device__ __forceinline__ uint32_t pack_h2(float x, float y) {
    __half2 h = __floats2half2_rn(x, y);
    return *(uint32_t*)&h;
}

// ===========================================================================
// Conversion kernels (fp32 -> fp16)
// ===========================================================================
__global__ void conv_x(const float* __restrict__ in, __half* __restrict__ o) {
    int i = (blockIdx.x * 256 + threadIdx.x) * 4;
    float4 v = *(const float4*)(in + i);
    *(uint2*)(o + i) = make_uint2(pack_h2(v.x, v.y), pack_h2(v.z, v.w));
}

__global__ void conv_w(const float* __restrict__ W0, const float* __restrict__ W1,
                       const float* __restrict__ W2, const float* __restrict__ W3,
                       __half* __restrict__ w)
{
    const float* W = (blockIdx.y == 0) ? W0 : (blockIdx.y == 1) ? W1
                   : (blockIdx.y == 2) ? W2 : W3;
    size_t base = (size_t)blockIdx.y * DM_ * DM_;
    int i = (blockIdx.x * 256 + threadIdx.x) * 4;
    float4 v = *(const float4*)(W + i);
    *(uint2*)(w + base + i) = make_uint2(pack_h2(v.x, v.y), pack_h2(v.z, v.w));
}

// ===========================================================================
// fp16 single-pass GEMM: C = A_f16 * W_f16.  128x128 tile, BK=32,
// cp.async 2-stage, 2 CTA/SM. B via ldmatrix.trans from [K,N] layout.
// MODE 0: QKV — RoPE epilogue; q/k/v single fp16.
// MODE 1: out-proj, fp32 epilogue.
// ===========================================================================
#define GP      80                    // A smem row pitch
#define TSZA    (128 * GP)            // A tile: 10240 B
#define PITB    272                   // B smem row pitch (128 fp16 + 16B pad)
#define TSZB    (32 * PITB)           // B tile: 8704 B
#define STG     (TSZA + TSZB)         // 18944 per stage
#define G_SMEM  (2 * STG)             // 37888

#define QSCALE  0.1803368801111204f   // 0.125 * log2(e)

template<int MODE>
__global__ __launch_bounds__(256, 2) void gemm128(
    const __half* __restrict__ Ap, const __half* __restrict__ Wp,
    const float* __restrict__ cs, const float* __restrict__ sn,
    float* __restrict__ Cf,
    __half* __restrict__ qq, __half* __restrict__ kq, __half* __restrict__ vq)
{
    extern __shared__ __align__(16) char sm[];
    const int tid  = threadIdx.x;
    const int wid  = tid >> 5;
    const int lane = tid & 31;
    const int wm   = wid & 3;
    const int wn   = wid >> 2;
    const int widx = (MODE == 0) ? (blockIdx.x >> 3) : 3;
    const int n0   = (blockIdx.x & 7) * 128;
    const int m0   = blockIdx.y * 128;
    const uint32_t sb = smem_u32(sm);

    const __half* gA = Ap + (size_t)m0 * DM_;
    const __half* gW = Wp + (size_t)widx * DM_ * DM_ + n0;

    const int arow = tid >> 2;         // 0..63
    const int acg  = tid & 3;
    const int brow = tid >> 4;         // 0..15
    const int bcg  = tid & 15;

    #define ISSUE(st_, k0_)                                                    \
        {                                                                      \
            uint32_t dA = sb + (st_) * STG + arow * GP + acg * 16;             \
            const __half* ga = gA + (size_t)arow * DM_ + (k0_) + acg * 8;      \
            CP_ASYNC16(dA,           ga);                                      \
            CP_ASYNC16(dA + 64 * GP, ga + (size_t)64 * DM_);                   \
            uint32_t dB = sb + (st_) * STG + TSZA + brow * PITB + bcg * 16;    \
            const __half* gb = gW + (size_t)((k0_) + brow) * DM_ + bcg * 8;    \
            CP_ASYNC16(dB,             gb);                                    \
            CP_ASYNC16(dB + 16 * PITB, gb + (size_t)16 * DM_);                 \
            CP_COMMIT();                                                       \
        }

    const uint32_t a_off = (uint32_t)((lane & 15) * GP + (lane >> 4) * 16);
    const uint32_t b_off = (uint32_t)((lane & 7) * PITB +
                                      ((lane >> 3) & 1) * 8 * PITB + (lane >> 4) * 16);

    float acc[2][8][4];
    #pragma unroll
    for (int i = 0; i < 2; i++)
        #pragma unroll
        for (int j = 0; j < 8; j++)
            #pragma unroll
            for (int l = 0; l < 4; l++) acc[i][j][l] = 0.f;

    ISSUE(0, 0);
    ISSUE(1, 32);

    const int NIT = DM_ / 32;   // 32
    for (int c = 0; c < NIT; c++) {
        if (c + 1 < NIT) { CP_WAIT1(); } else { CP_WAIT0(); }
        __syncthreads();

        const uint32_t stb = sb + (c & 1) * STG;
        #pragma unroll
        for (int ks = 0; ks < 2; ks++) {
            uint32_t af[2][4];
            #pragma unroll
            for (int mt = 0; mt < 2; mt++)
                ldsm4(af[mt], stb + (uint32_t)((wm * 32 + mt * 16) * GP + ks * 32) + a_off);
            #pragma unroll
            for (int nt = 0; nt < 4; nt++) {
                uint32_t bb = stb + TSZA + (uint32_t)(ks * 16 * PITB +
                              wn * 128 + nt * 32) + b_off;
                uint32_t th[4];
                ldsm4t(th, bb);
                #pragma unroll
                for (int mt = 0; mt < 2; mt++) {
                    mma16816h(acc[mt][2*nt],   af[mt], th);
                    mma16816h(acc[mt][2*nt+1], af[mt], th + 2);
                }
            }
        }
        __syncthreads();
        if (c + 2 < NIT) { ISSUE((c & 1), (c + 2) * 32); }
    }

    // ---- epilogue ----
    if (MODE == 1) {
        #pragma unroll
        for (int mt = 0; mt < 2; mt++) {
            int m = m0 + wm * 32 + mt * 16 + (lane >> 2);
            #pragma unroll
            for (int nt = 0; nt < 8; nt++) {
                int n = n0 + wn * 64 + nt * 8 + (lane & 3) * 2;
                *(float2*)(Cf + (size_t)m * DM_ + n) =
                    make_float2(acc[mt][nt][0], acc[mt][nt][1]);
                *(float2*)(Cf + (size_t)(m + 8) * DM_ + n) =
                    make_float2(acc[mt][nt][2], acc[mt][nt][3]);
            }
        }
    } else {
        __half* d = (widx == 0) ? qq : (widx == 1) ? kq : vq;
        #pragma unroll
        for (int mt = 0; mt < 2; mt++) {
            int m  = m0 + wm * 32 + mt * 16 + (lane >> 2);
            int t0 = m & (T_ - 1);
            int t1 = (m + 8) & (T_ - 1);
            #pragma unroll
            for (int nt = 0; nt < 8; nt++) {
                int n = n0 + wn * 64 + nt * 8 + (lane & 3) * 2;
                float e0 = acc[mt][nt][0], o0 = acc[mt][nt][1];
                float e1 = acc[mt][nt][2], o1 = acc[mt][nt][3];
                if (widx <= 1) {       // rope on q, k (q also scaled for exp2)
                    int i = (n & 63) >> 1;
                    float c0 = __ldg(cs + t0 * 32 + i), s0 = __ldg(sn + t0 * 32 + i);
                    float c1 = __ldg(cs + t1 * 32 + i), s1 = __ldg(sn + t1 * 32 + i);
                    float sc = (widx == 0) ? QSCALE : 1.f;
                    float a0 = (e0 * c0 - o0 * s0) * sc, b0 = (e0 * s0 + o0 * c0) * sc;
                    float a1 = (e1 * c1 - o1 * s1) * sc, b1 = (e1 * s1 + o1 * c1) * sc;
                    e0 = a0; o0 = b0; e1 = a1; o1 = b1;
                }
                *(uint32_t*)(d + (size_t)m * DM_ + n)       = pack_h2(e0, o0);
                *(uint32_t*)(d + (size_t)(m + 8) * DM_ + n) = pack_h2(e1, o1);
            }
        }
    }
    #undef ISSUE
}

// ===========================================================================
// Tensor-core flash attention (fp16 single-pass, causal, exp2 SOFF=0).
// QK: q_f16 · k_f16 ; PV: p_f16 · v_f16 (fp32 accum throughout).
// Balanced CTA pairs (15-bx, bx): 34 k-tiles each; 2 CTA/SM.
// ===========================================================================
#define PIT   144
#define V_O   9216                  // V tile offset within stage
#define AST   18432                 // stage size (K + V tiles)
#define ATT_SMEM (2 * AST)          // 36864

__global__ __launch_bounds__(256, 2) void attn_mma(
    const __half* __restrict__ qq, const __half* __restrict__ kq,
    const __half* __restrict__ vq, __half* __restrict__ zq)
{
    extern __shared__ __align__(16) char sm[];
    const int tid  = threadIdx.x;
    const int lane = tid & 31;
    const int wq   = tid >> 5;
    const int bx   = blockIdx.x;          // 0..7
    const int bh_  = blockIdx.y;
    const int b    = bh_ >> 4;
    const int h    = bh_ & 15;
    const int bT   = b * T_;
    const uint32_t sb = smem_u32(sm);
    const size_t hcol = (size_t)h * DH_;

    const uint32_t k_off = ((lane >> 4) * 8 + (lane & 7)) * PIT + ((lane >> 3) & 1) * 16;
    const uint32_t v_off = (lane & 7) * PIT + ((lane >> 3) & 1) * 8 * PIT + (lane >> 4) * 16;

    #define AISSUE(st_, k0_)                                                   \
        {                                                                      \
            int r = tid >> 3, cc = tid & 7;                                    \
            uint32_t d = sb + (st_) * AST + r * PIT + cc * 16;                 \
            size_t g = ((size_t)(bT + (k0_) + r)) * DM_ + hcol + cc * 8;       \
            CP_ASYNC16(d,                  kq + g);                            \
            CP_ASYNC16(d + 32 * PIT,       kq + g + 32 * DM_);                 \
            CP_ASYNC16(d + V_O,            vq + g);                            \
            CP_ASYNC16(d + V_O + 32 * PIT, vq + g + 32 * DM_);                 \
            CP_COMMIT();                                                       \
        }

    #pragma unroll 1
    for (int ph = 0; ph < 2; ph++) {
        const int qi = ph ? bx : 15 - bx;     // heavy tile first
        const int q0 = qi * 128;
        const int nkt = 2 * qi + 2;
        const int qg_lo = q0 + wq * 16 + (lane >> 2);
        const int qg_hi = qg_lo + 8;

        // ---- stage Q through smem, extract A-fragments ----
        {
            int r = tid >> 3, c = tid & 7;
            #pragma unroll
            for (int i = 0; i < 4; i++) {
                int row = r + i * 32;
                size_t g = ((size_t)(bT + q0 + row)) * DM_ + hcol + c * 8;
                *(uint4*)(sm + row * PIT + c * 16) = *(const uint4*)(qq + g);
            }
        }
        __syncthreads();

        uint32_t qf[4][4];
        {
            const uint32_t a_off = (lane & 15) * PIT + (lane >> 4) * 16;
            #pragma unroll
            for (int ks = 0; ks < 4; ks++)
                ldsm4(qf[ks], sb + (wq * 16) * PIT + ks * 32 + a_off);
        }
        __syncthreads();   // Q reads done; smem reusable for K/V stages

        AISSUE(0, 0);
        if (nkt > 1) AISSUE(1, 64);

        float o[8][4];
        #pragma unroll
        for (int i = 0; i < 8; i++)
            #pragma unroll
            for (int j = 0; j < 4; j++) o[i][j] = 0.f;
        float l_lo = 0.f, l_hi = 0.f;

        for (int kt = 0; kt < nkt; kt++) {
            const int k0 = kt * 64;
            if (kt + 1 < nkt) { CP_WAIT1(); } else { CP_WAIT0(); }
            __syncthreads();
            const uint32_t stb = sb + (kt & 1) * AST;

            // ---- S' = Q' K^T (single pass) ----
            float sf[8][4];
            #pragma unroll
            for (int i = 0; i < 8; i++)
                #pragma unroll
                for (int j = 0; j < 4; j++) sf[i][j] = 0.f;

            #pragma unroll
            for (int ks = 0; ks < 4; ks++) {
                #pragma unroll
                for (int nt2 = 0; nt2 < 4; nt2++) {
                    uint32_t th[4];
                    ldsm4(th, stb + (nt2 * 16) * PIT + ks * 32 + k_off);
                    mma16816h(sf[2*nt2],   qf[ks], th);
                    mma16816h(sf[2*nt2+1], qf[ks], th + 2);
                }
            }

            if (kt >= nkt - 2) {
                #pragma unroll
                for (int nt = 0; nt < 8; nt++) {
                    int kg = k0 + nt * 8 + (lane & 3) * 2;
                    if (kg     > qg_lo) sf[nt][0] = -1e30f;
                    if (kg + 1 > qg_lo) sf[nt][1] = -1e30f;
                    if (kg     > qg_hi) sf[nt][2] = -1e30f;
                    if (kg + 1 > qg_hi) sf[nt][3] = -1e30f;
                }
            }

            // ---- p = 2^s' (|s'|<=~13 fits fp16); accumulate l per-thread ----
            #pragma unroll
            for (int nt = 0; nt < 8; nt++) {
                sf[nt][0] = ex2f(sf[nt][0]);
                sf[nt][1] = ex2f(sf[nt][1]);
                sf[nt][2] = ex2f(sf[nt][2]);
                sf[nt][3] = ex2f(sf[nt][3]);
                l_lo += sf[nt][0] + sf[nt][1];
                l_hi += sf[nt][2] + sf[nt][3];
            }

            // ---- O += P V (single pass) ----
            #pragma unroll
            for (int j = 0; j < 4; j++) {
                uint32_t pf[4];
                pf[0] = pack_h2(sf[2*j][0],   sf[2*j][1]);
                pf[1] = pack_h2(sf[2*j][2],   sf[2*j][3]);
                pf[2] = pack_h2(sf[2*j+1][0], sf[2*j+1][1]);
                pf[3] = pack_h2(sf[2*j+1][2], sf[2*j+1][3]);
                #pragma unroll
                for (int d2 = 0; d2 < 4; d2++) {
                    uint32_t th[4];
                    ldsm4t(th, stb + V_O + (j * 16) * PIT + d2 * 32 + v_off);
                    mma16816h(o[2*d2],   pf, th);
                    mma16816h(o[2*d2+1], pf, th + 2);
                }
            }

            __syncthreads();
            if (kt + 2 < nkt) { AISSUE((kt & 1), (kt + 2) * 64); }
        }

        // ---- epilogue: reduce l across quad lanes, normalize, write fp16 z ----
        l_lo += __shfl_xor_sync(0xffffffffu, l_lo, 1);
        l_lo += __shfl_xor_sync(0xffffffffu, l_lo, 2);
        l_hi += __shfl_xor_sync(0xffffffffu, l_hi, 1);
        l_hi += __shfl_xor_sync(0xffffffffu, l_hi, 2);
        float il_lo = 1.f / l_lo, il_hi = 1.f / l_hi;
        size_t out_lo = ((size_t)(bT + qg_lo)) * DM_ + hcol + (lane & 3) * 2;
        #pragma unroll
        for (int nt = 0; nt < 8; nt++) {
            *(uint32_t*)(zq + out_lo + nt * 8) =
                pack_h2(o[nt][0] * il_lo, o[nt][1] * il_lo);
            *(uint32_t*)(zq + out_lo + 8 * DM_ + nt * 8) =
                pack_h2(o[nt][2] * il_hi, o[nt][3] * il_hi);
        }
    }
    #undef AISSUE
}

// ---------------------------------------------------------------------------
extern "C" void kernel_launch(void* const* d_in, const int* in_sizes, int n_in,
                              void* d_out, int out_size)
{
    const float* x  = (const float*)d_in[0];
    const float* cs = (const float*)d_in[1];
    const float* sn = (const float*)d_in[2];
    const float* Wq = (const float*)d_in[3];
    const float* Wk = (const float*)d_in[4];
    const float* Wv = (const float*)d_in[5];
    const float* Wo = (const float*)d_in[6];
    float* out = (float*)d_out;

    __half *xp, *wp, *qp, *kp, *vp, *zp;
    cudaGetSymbolAddress((void**)&xp, g_x);
    cudaGetSymbolAddress((void**)&wp, g_w);
    cudaGetSymbolAddress((void**)&qp, g_q);
    cudaGetSymbolAddress((void**)&kp, g_k);
    cudaGetSymbolAddress((void**)&vp, g_v);
    cudaGetSymbolAddress((void**)&zp, g_z);

    cudaFuncSetAttribute(gemm128<0>, cudaFuncAttributeMaxDynamicSharedMemorySize, G_SMEM);
    cudaFuncSetAttribute(gemm128<1>, cudaFuncAttributeMaxDynamicSharedMemorySize, G_SMEM);
    cudaFuncSetAttribute(attn_mma, cudaFuncAttributeMaxDynamicSharedMemorySize, ATT_SMEM);

    // fp32 -> fp16 conversions
    conv_x<<<BT_ * DM_ / 1024, 256>>>(x, xp);
    conv_w<<<dim3(DM_ * DM_ / 1024, 4), 256>>>(Wq, Wk, Wv, Wo, wp);

    // fused QKV GEMM + RoPE epilogue (q/k/v single fp16)
    gemm128<0><<<dim3(24, BT_ / 128), 256, G_SMEM>>>(
        xp, wp, cs, sn, nullptr, qp, kp, vp);

    attn_mma<<<dim3(8, B_ * H_), 256, ATT_SMEM>>>(qp, kp, vp, zp);

    // out = z Wo
    gemm128<1><<<dim3(8, BT_ / 128), 256, G_SMEM>>>(
        zp, wp, cs, sn, out, nullptr, nullptr, nullptr);
}

// round 12
// speedup vs baseline: 2.8124x; 1.0561x over previous
#include <cuda_runtime.h>
#include <cuda_fp16.h>
#include <cstdint>

#define B_   2
#define T_   2048
#define DM_  1024
#define H_   16
#define DH_  64
#define BT_  (B_ * T_)   // 4096

// Scratch (allocation-free rule: device globals) — all single fp16
__device__ __half g_x[BT_ * DM_];
__device__ __half g_w[4 * DM_ * DM_];                 // W fp16, [K,N], 4 slabs
__device__ __half g_q[BT_ * DM_];
__device__ __half g_k[BT_ * DM_];
__device__ __half g_v[BT_ * DM_];
__device__ __half g_z[BT_ * DM_];

// ===========================================================================
// Warp-MMA + cp.async helpers
// ===========================================================================
__device__ __forceinline__ uint32_t smem_u32(const void* p) {
    uint32_t a;
    asm("{ .reg .u64 t; cvta.to.shared.u64 t, %1; cvt.u32.u64 %0, t; }"
        : "=r"(a) : "l"(p));
    return a;
}

__device__ __forceinline__ void ldsm4(uint32_t* r, uint32_t addr) {
    asm volatile("ldmatrix.sync.aligned.m8n8.x4.shared.b16 {%0,%1,%2,%3}, [%4];"
                 : "=r"(r[0]), "=r"(r[1]), "=r"(r[2]), "=r"(r[3]) : "r"(addr));
}
__device__ __forceinline__ void ldsm4t(uint32_t* r, uint32_t addr) {
    asm volatile("ldmatrix.sync.aligned.m8n8.x4.trans.shared.b16 {%0,%1,%2,%3}, [%4];"
                 : "=r"(r[0]), "=r"(r[1]), "=r"(r[2]), "=r"(r[3]) : "r"(addr));
}

__device__ __forceinline__ void mma16816h(float* c, const uint32_t* a,
                                          const uint32_t* b) {
    asm volatile(
        "mma.sync.aligned.m16n8k16.row.col.f32.f16.f16.f32 "
        "{%0,%1,%2,%3}, {%4,%5,%6,%7}, {%8,%9}, {%0,%1,%2,%3};"
        : "+f"(c[0]), "+f"(c[1]), "+f"(c[2]), "+f"(c[3])
        : "r"(a[0]), "r"(a[1]), "r"(a[2]), "r"(a[3]), "r"(b[0]), "r"(b[1]));
}

#define CP_ASYNC16(dst, src) \
    asm volatile("cp.async.cg.shared.global [%0], [%1], 16;" :: "r"(dst), "l"(src))
#define CP_COMMIT() asm volatile("cp.async.commit_group;")
#define CP_WAIT1()  asm volatile("cp.async.wait_group 1;")
#define CP_WAIT0()  asm volatile("cp.async.wait_group 0;")

__device__ __forceinline__ float ex2f(float x) {
    float y;
    asm("ex2.approx.f32 %0, %1;" : "=f"(y) : "f"(x));
    return y;
}

__device__ __forceinline__ uint32_t pack_h2(float x, float y) {
    __half2 h = __floats2half2_rn(x, y);
    return *(uint32_t*)&h;
}

// ===========================================================================
// Fused conversion kernel (x + 4 weight slabs), fp32 -> fp16
// grid (1024, 8): y<4 -> W slab y ; y>=4 -> x quarter (y-4)
// ===========================================================================
__global__ void conv_all(const float* __restrict__ x,
                         const float* __restrict__ W0, const float* __restrict__ W1,
                         const float* __restrict__ W2, const float* __restrict__ W3,
                         __half* __restrict__ xo, __half* __restrict__ wo)
{
    int y = blockIdx.y;
    const float* src;
    __half* dst;
    size_t base;
    if (y < 4) {
        src = (y == 0) ? W0 : (y == 1) ? W1 : (y == 2) ? W2 : W3;
        dst = wo;
        base = (size_t)y * DM_ * DM_;
        base += (size_t)(blockIdx.x * 256 + threadIdx.x) * 4;
        float4 v = *(const float4*)(src + (size_t)(blockIdx.x * 256 + threadIdx.x) * 4);
        *(uint2*)(dst + base) = make_uint2(pack_h2(v.x, v.y), pack_h2(v.z, v.w));
    } else {
        size_t i = ((size_t)(y - 4) * 1024 + blockIdx.x) * 1024 +
                   (size_t)threadIdx.x * 4;
        float4 v = *(const float4*)(x + i);
        *(uint2*)(xo + i) = make_uint2(pack_h2(v.x, v.y), pack_h2(v.z, v.w));
    }
}

// ===========================================================================
// fp16 single-pass GEMM: 128x128 tile, BK=32, cp.async 3-stage ring,
// ONE __syncthreads per k-iteration. 2 CTA/SM.
// MODE 0: QKV — RoPE epilogue. MODE 1: out-proj, fp32 epilogue.
// ===========================================================================
#define GP      80
#define TSZA    (128 * GP)            // 10240
#define PITB    272
#define TSZB    (32 * PITB)           // 8704
#define STG     (TSZA + TSZB)         // 18944 per stage
#define G_SMEM  (3 * STG)             // 56832

#define QSCALE  0.1803368801111204f   // 0.125 * log2(e)

template<int MODE>
__global__ __launch_bounds__(256, 2) void gemm128(
    const __half* __restrict__ Ap, const __half* __restrict__ Wp,
    const float* __restrict__ cs, const float* __restrict__ sn,
    float* __restrict__ Cf,
    __half* __restrict__ qq, __half* __restrict__ kq, __half* __restrict__ vq)
{
    extern __shared__ __align__(16) char sm[];
    const int tid  = threadIdx.x;
    const int wid  = tid >> 5;
    const int lane = tid & 31;
    const int wm   = wid & 3;
    const int wn   = wid >> 2;
    const int widx = (MODE == 0) ? (blockIdx.x >> 3) : 3;
    const int n0   = (blockIdx.x & 7) * 128;
    const int m0   = blockIdx.y * 128;
    const uint32_t sb = smem_u32(sm);

    const __half* gA = Ap + (size_t)m0 * DM_;
    const __half* gW = Wp + (size_t)widx * DM_ * DM_ + n0;

    const int arow = tid >> 2;
    const int acg  = tid & 3;
    const int brow = tid >> 4;
    const int bcg  = tid & 15;

    #define ISSUE(st_, k0_)                                                    \
        {                                                                      \
            uint32_t dA = sb + (st_) * STG + arow * GP + acg * 16;             \
            const __half* ga = gA + (size_t)arow * DM_ + (k0_) + acg * 8;      \
            CP_ASYNC16(dA,           ga);                                      \
            CP_ASYNC16(dA + 64 * GP, ga + (size_t)64 * DM_);                   \
            uint32_t dB = sb + (st_) * STG + TSZA + brow * PITB + bcg * 16;    \
            const __half* gb = gW + (size_t)((k0_) + brow) * DM_ + bcg * 8;    \
            CP_ASYNC16(dB,             gb);                                    \
            CP_ASYNC16(dB + 16 * PITB, gb + (size_t)16 * DM_);                 \
            CP_COMMIT();                                                       \
        }

    const uint32_t a_off = (uint32_t)((lane & 15) * GP + (lane >> 4) * 16);
    const uint32_t b_off = (uint32_t)((lane & 7) * PITB +
                                      ((lane >> 3) & 1) * 8 * PITB + (lane >> 4) * 16);

    float acc[2][8][4];
    #pragma unroll
    for (int i = 0; i < 2; i++)
        #pragma unroll
        for (int j = 0; j < 8; j++)
            #pragma unroll
            for (int l = 0; l < 4; l++) acc[i][j][l] = 0.f;

    ISSUE(0, 0);
    ISSUE(1, 32);

    const int NIT = DM_ / 32;   // 32
    for (int c = 0; c < NIT; c++) {
        if (c + 1 < NIT) { CP_WAIT1(); } else { CP_WAIT0(); }
        __syncthreads();
        if (c + 2 < NIT) { ISSUE((c + 2) % 3, (c + 2) * 32); }

        const uint32_t stb = sb + (c % 3) * STG;
        #pragma unroll
        for (int ks = 0; ks < 2; ks++) {
            uint32_t af[2][4];
            #pragma unroll
            for (int mt = 0; mt < 2; mt++)
                ldsm4(af[mt], stb + (uint32_t)((wm * 32 + mt * 16) * GP + ks * 32) + a_off);
            #pragma unroll
            for (int nt = 0; nt < 4; nt++) {
                uint32_t bb = stb + TSZA + (uint32_t)(ks * 16 * PITB +
                              wn * 128 + nt * 32) + b_off;
                uint32_t th[4];
                ldsm4t(th, bb);
                #pragma unroll
                for (int mt = 0; mt < 2; mt++) {
                    mma16816h(acc[mt][2*nt],   af[mt], th);
                    mma16816h(acc[mt][2*nt+1], af[mt], th + 2);
                }
            }
        }
    }

    // ---- epilogue ----
    if (MODE == 1) {
        #pragma unroll
        for (int mt = 0; mt < 2; mt++) {
            int m = m0 + wm * 32 + mt * 16 + (lane >> 2);
            #pragma unroll
            for (int nt = 0; nt < 8; nt++) {
                int n = n0 + wn * 64 + nt * 8 + (lane & 3) * 2;
                *(float2*)(Cf + (size_t)m * DM_ + n) =
                    make_float2(acc[mt][nt][0], acc[mt][nt][1]);
                *(float2*)(Cf + (size_t)(m + 8) * DM_ + n) =
                    make_float2(acc[mt][nt][2], acc[mt][nt][3]);
            }
        }
    } else {
        __half* d = (widx == 0) ? qq : (widx == 1) ? kq : vq;
        #pragma unroll
        for (int mt = 0; mt < 2; mt++) {
            int m  = m0 + wm * 32 + mt * 16 + (lane >> 2);
            int t0 = m & (T_ - 1);
            int t1 = (m + 8) & (T_ - 1);
            #pragma unroll
            for (int nt = 0; nt < 8; nt++) {
                int n = n0 + wn * 64 + nt * 8 + (lane & 3) * 2;
                float e0 = acc[mt][nt][0], o0 = acc[mt][nt][1];
                float e1 = acc[mt][nt][2], o1 = acc[mt][nt][3];
                if (widx <= 1) {
                    int i = (n & 63) >> 1;
                    float c0 = __ldg(cs + t0 * 32 + i), s0 = __ldg(sn + t0 * 32 + i);
                    float c1 = __ldg(cs + t1 * 32 + i), s1 = __ldg(sn + t1 * 32 + i);
                    float sc = (widx == 0) ? QSCALE : 1.f;
                    float a0 = (e0 * c0 - o0 * s0) * sc, b0 = (e0 * s0 + o0 * c0) * sc;
                    float a1 = (e1 * c1 - o1 * s1) * sc, b1 = (e1 * s1 + o1 * c1) * sc;
                    e0 = a0; o0 = b0; e1 = a1; o1 = b1;
                }
                *(uint32_t*)(d + (size_t)m * DM_ + n)       = pack_h2(e0, o0);
                *(uint32_t*)(d + (size_t)(m + 8) * DM_ + n) = pack_h2(e1, o1);
            }
        }
    }
    #undef ISSUE
}

// ===========================================================================
// Tensor-core flash attention (fp16 single-pass, causal, exp2 SOFF=0).
// Fused per-strip pipeline: QK(nt2) -> softmax(nt2) -> PV(nt2), so the next
// strip's QK MMAs overlap this strip's MUFU/ALU softmax.
// 3-stage cp.async ring; ONE __syncthreads per k-tile.
// Balanced CTA pairs (15-bx, bx): 34 k-tiles each; 2 CTA/SM.
// ===========================================================================
#define PIT   144
#define V_O   9216
#define AST   18432                 // stage size (K + V tiles)
#define ATT_SMEM (3 * AST)          // 55296

__global__ __launch_bounds__(256, 2) void attn_mma(
    const __half* __restrict__ qq, const __half* __restrict__ kq,
    const __half* __restrict__ vq, __half* __restrict__ zq)
{
    extern __shared__ __align__(16) char sm[];
    const int tid  = threadIdx.x;
    const int lane = tid & 31;
    const int wq   = tid >> 5;
    const int bx   = blockIdx.x;          // 0..7
    const int bh_  = blockIdx.y;
    const int b    = bh_ >> 4;
    const int h    = bh_ & 15;
    const int bT   = b * T_;
    const uint32_t sb = smem_u32(sm);
    const size_t hcol = (size_t)h * DH_;

    const uint32_t k_off = ((lane >> 4) * 8 + (lane & 7)) * PIT + ((lane >> 3) & 1) * 16;
    const uint32_t v_off = (lane & 7) * PIT + ((lane >> 3) & 1) * 8 * PIT + (lane >> 4) * 16;

    #define AISSUE(st_, k0_)                                                   \
        {                                                                      \
            int r = tid >> 3, cc = tid & 7;                                    \
            uint32_t d = sb + (st_) * AST + r * PIT + cc * 16;                 \
            size_t g = ((size_t)(bT + (k0_) + r)) * DM_ + hcol + cc * 8;       \
            CP_ASYNC16(d,                  kq + g);                            \
            CP_ASYNC16(d + 32 * PIT,       kq + g + 32 * DM_);                 \
            CP_ASYNC16(d + V_O,            vq + g);                            \
            CP_ASYNC16(d + V_O + 32 * PIT, vq + g + 32 * DM_);                 \
            CP_COMMIT();                                                       \
        }

    #pragma unroll 1
    for (int ph = 0; ph < 2; ph++) {
        const int qi = ph ? bx : 15 - bx;     // heavy tile first
        const int q0 = qi * 128;
        const int nkt = 2 * qi + 2;
        const int qg_lo = q0 + wq * 16 + (lane >> 2);
        const int qg_hi = qg_lo + 8;

        __syncthreads();    // all warps done reading previous phase's smem

        // ---- stage Q through smem, extract A-fragments ----
        {
            int r = tid >> 3, c = tid & 7;
            #pragma unroll
            for (int i = 0; i < 4; i++) {
                int row = r + i * 32;
                size_t g = ((size_t)(bT + q0 + row)) * DM_ + hcol + c * 8;
                *(uint4*)(sm + row * PIT + c * 16) = *(const uint4*)(qq + g);
            }
        }
        __syncthreads();

        uint32_t qf[4][4];
        {
            const uint32_t a_off = (lane & 15) * PIT + (lane >> 4) * 16;
            #pragma unroll
            for (int ks = 0; ks < 4; ks++)
                ldsm4(qf[ks], sb + (wq * 16) * PIT + ks * 32 + a_off);
        }
        __syncthreads();   // Q reads done; smem reusable for K/V stages

        AISSUE(0, 0);
        if (nkt > 1) AISSUE(1, 64);

        float o[8][4];
        #pragma unroll
        for (int i = 0; i < 8; i++)
            #pragma unroll
            for (int j = 0; j < 4; j++) o[i][j] = 0.f;
        float l_lo = 0.f, l_hi = 0.f;

        for (int kt = 0; kt < nkt; kt++) {
            const int k0 = kt * 64;
            if (kt + 1 < nkt) { CP_WAIT1(); } else { CP_WAIT0(); }
            __syncthreads();
            if (kt + 2 < nkt) { AISSUE((kt + 2) % 3, (kt + 2) * 64); }

            const uint32_t stb = sb + (kt % 3) * AST;
            const bool diag = (kt >= nkt - 2);

            #pragma unroll
            for (int nt2 = 0; nt2 < 4; nt2++) {
                // ---- QK strip: S'[16 cols] ----
                float s0[4] = {0.f, 0.f, 0.f, 0.f};
                float s1[4] = {0.f, 0.f, 0.f, 0.f};
                #pragma unroll
                for (int ks = 0; ks < 4; ks++) {
                    uint32_t th[4];
                    ldsm4(th, stb + (nt2 * 16) * PIT + ks * 32 + k_off);
                    mma16816h(s0, qf[ks], th);
                    mma16816h(s1, qf[ks], th + 2);
                }

                if (diag) {
                    int kg = k0 + nt2 * 16 + (lane & 3) * 2;
                    if (kg     > qg_lo) s0[0] = -1e30f;
                    if (kg + 1 > qg_lo) s0[1] = -1e30f;
                    if (kg     > qg_hi) s0[2] = -1e30f;
                    if (kg + 1 > qg_hi) s0[3] = -1e30f;
                    if (kg + 8 > qg_lo) s1[0] = -1e30f;
                    if (kg + 9 > qg_lo) s1[1] = -1e30f;
                    if (kg + 8 > qg_hi) s1[2] = -1e30f;
                    if (kg + 9 > qg_hi) s1[3] = -1e30f;
                }

                // ---- softmax strip: p = 2^s' ----
                s0[0] = ex2f(s0[0]); s0[1] = ex2f(s0[1]);
                s0[2] = ex2f(s0[2]); s0[3] = ex2f(s0[3]);
                s1[0] = ex2f(s1[0]); s1[1] = ex2f(s1[1]);
                s1[2] = ex2f(s1[2]); s1[3] = ex2f(s1[3]);
                l_lo += s0[0] + s0[1] + s1[0] + s1[1];
                l_hi += s0[2] + s0[3] + s1[2] + s1[3];

                uint32_t pf[4];
                pf[0] = pack_h2(s0[0], s0[1]);
                pf[1] = pack_h2(s0[2], s0[3]);
                pf[2] = pack_h2(s1[0], s1[1]);
                pf[3] = pack_h2(s1[2], s1[3]);

                // ---- PV strip ----
                #pragma unroll
                for (int d2 = 0; d2 < 4; d2++) {
                    uint32_t tv[4];
                    ldsm4t(tv, stb + V_O + (nt2 * 16) * PIT + d2 * 32 + v_off);
                    mma16816h(o[2*d2],   pf, tv);
                    mma16816h(o[2*d2+1], pf, tv + 2);
                }
            }
        }

        // ---- epilogue: reduce l across quad lanes, normalize, write fp16 z ----
        l_lo += __shfl_xor_sync(0xffffffffu, l_lo, 1);
        l_lo += __shfl_xor_sync(0xffffffffu, l_lo, 2);
        l_hi += __shfl_xor_sync(0xffffffffu, l_hi, 1);
        l_hi += __shfl_xor_sync(0xffffffffu, l_hi, 2);
        float il_lo = 1.f / l_lo, il_hi = 1.f / l_hi;
        size_t out_lo = ((size_t)(bT + qg_lo)) * DM_ + hcol + (lane & 3) * 2;
        #pragma unroll
        for (int nt = 0; nt < 8; nt++) {
            *(uint32_t*)(zq + out_lo + nt * 8) =
                pack_h2(o[nt][0] * il_lo, o[nt][1] * il_lo);
            *(uint32_t*)(zq + out_lo + 8 * DM_ + nt * 8) =
                pack_h2(o[nt][2] * il_hi, o[nt][3] * il_hi);
        }
    }
    #undef AISSUE
}

// ---------------------------------------------------------------------------
extern "C" void kernel_launch(void* const* d_in, const int* in_sizes, int n_in,
                              void* d_out, int out_size)
{
    const float* x  = (const float*)d_in[0];
    const float* cs = (const float*)d_in[1];
    const float* sn = (const float*)d_in[2];
    const float* Wq = (const float*)d_in[3];
    const float* Wk = (const float*)d_in[4];
    const float* Wv = (const float*)d_in[5];
    const float* Wo = (const float*)d_in[6];
    float* out = (float*)d_out;

    __half *xp, *wp, *qp, *kp, *vp, *zp;
    cudaGetSymbolAddress((void**)&xp, g_x);
    cudaGetSymbolAddress((void**)&wp, g_w);
    cudaGetSymbolAddress((void**)&qp, g_q);
    cudaGetSymbolAddress((void**)&kp, g_k);
    cudaGetSymbolAddress((void**)&vp, g_v);
    cudaGetSymbolAddress((void**)&zp, g_z);

    cudaFuncSetAttribute(gemm128<0>, cudaFuncAttributeMaxDynamicSharedMemorySize, G_SMEM);
    cudaFuncSetAttribute(gemm128<1>, cudaFuncAttributeMaxDynamicSharedMemorySize, G_SMEM);
    cudaFuncSetAttribute(attn_mma, cudaFuncAttributeMaxDynamicSharedMemorySize, ATT_SMEM);

    // fp32 -> fp16 conversions (one launch: x + 4 weight slabs)
    conv_all<<<dim3(1024, 8), 256>>>(x, Wq, Wk, Wv, Wo, xp, wp);

    // fused QKV GEMM + RoPE epilogue
    gemm128<0><<<dim3(24, BT_ / 128), 256, G_SMEM>>>(
        xp, wp, cs, sn, nullptr, qp, kp, vp);

    attn_mma<<<dim3(8, B_ * H_), 256, ATT_SMEM>>>(qp, kp, vp, zp);

    // out = z Wo
    gemm128<1><<<dim3(8, BT_ / 128), 256, G_SMEM>>>(
        zp, wp, cs, sn, out, nullptr, nullptr, nullptr);
}